// round 11
// baseline (speedup 1.0000x reference)
#include <cuda_runtime.h>
#include <cuda_bf16.h>
#include <cstdint>
#include <cstddef>

// Problem constants
#define B_   4
#define N_   4096
#define E_   256
#define F_   256
#define MAXE 50
#define H1_  128
#define H2_  64
#define OUTC 512

// ---------------------------------------------------------------------------
// Static device scratch
// ---------------------------------------------------------------------------
__device__ float g_v [B_ * N_ * F_];                 // v fp32 (16 MB)
__device__ __nv_bfloat16 g_Sb[67108864];             // scores bf16 (128 MB)
__device__ __nv_bfloat16 g_xh [B_ * N_ * F_];        // x hi
__device__ __nv_bfloat16 g_xl [B_ * N_ * F_];        // x lo
__device__ __nv_bfloat16 g_xph[B_ * N_ * F_];        // xp hi
__device__ __nv_bfloat16 g_xpl[B_ * N_ * F_];
__device__ __nv_bfloat16 g_vth[B_ * F_ * N_];        // v^T hi  [b][256][4096]
__device__ __nv_bfloat16 g_vtl[B_ * F_ * N_];
__device__ __nv_bfloat16 g_Ph [67108864];            // softmax(S) hi (128 MB)
__device__ __nv_bfloat16 g_Pl [67108864];            // softmax(S) lo (128 MB)
__device__ __nv_bfloat16 g_wth [F_ * F_], g_wtl [F_ * F_];   // weight^T hi/lo
__device__ __nv_bfloat16 g_wnth[F_ * F_], g_wntl[F_ * F_];   // Wn_w^T hi/lo
__device__ float g_mean[B_ * MAXE * F_];
__device__ float g_ctx [B_ * MAXE];
__device__ float g_deg [MAXE];

// ---------------------------------------------------------------------------
// PTX helpers (base sm_100-safe: mma.sync / ldmatrix / cp.async)
// ---------------------------------------------------------------------------
__device__ __forceinline__ uint32_t smem_u32(const void* p) {
    uint32_t a;
    asm("{ .reg .u64 t; cvta.to.shared.u64 t, %1; cvt.u32.u64 %0, t; }"
        : "=r"(a) : "l"(p));
    return a;
}
__device__ __forceinline__ void cp_async16(uint32_t s, const void* g) {
    asm volatile("cp.async.cg.shared.global [%0], [%1], 16;\n"
        :: "r"(s), "l"((unsigned long long)__cvta_generic_to_global(g)) : "memory");
}
__device__ __forceinline__ void cp_commit() {
    asm volatile("cp.async.commit_group;\n" ::: "memory");
}
__device__ __forceinline__ void cp_wait0() {
    asm volatile("cp.async.wait_group 0;\n" ::: "memory");
}
__device__ __forceinline__ void cp_wait1() {
    asm volatile("cp.async.wait_group 1;\n" ::: "memory");
}
__device__ __forceinline__ void ldmatrix_x4(uint32_t* r, uint32_t addr) {
    asm volatile("ldmatrix.sync.aligned.m8n8.x4.shared.b16 {%0,%1,%2,%3}, [%4];\n"
        : "=r"(r[0]), "=r"(r[1]), "=r"(r[2]), "=r"(r[3]) : "r"(addr));
}
__device__ __forceinline__ void mma_bf16(float* d, const uint32_t* a,
                                         uint32_t b0, uint32_t b1) {
    asm volatile(
        "mma.sync.aligned.m16n8k16.row.col.f32.bf16.bf16.f32 "
        "{%0,%1,%2,%3}, {%4,%5,%6,%7}, {%8,%9}, {%0,%1,%2,%3};\n"
        : "+f"(d[0]), "+f"(d[1]), "+f"(d[2]), "+f"(d[3])
        : "r"(a[0]), "r"(a[1]), "r"(a[2]), "r"(a[3]), "r"(b0), "r"(b1));
}

// ---------------------------------------------------------------------------
// 128x128 SYM GEMM (S-GEMM only) — unchanged working version.
// NPASS=2: AhBh + AlBh. bf16 out + mirrored transpose tile (symmetric S).
// ---------------------------------------------------------------------------
#define GEMM_SMEM (3 * 32768)

__global__ __launch_bounds__(256)
void gemm_sym(const __nv_bfloat16* __restrict__ Ah, const __nv_bfloat16* __restrict__ Al,
              __nv_bfloat16* __restrict__ C0, int K, int ldc,
              long long sA, long long sC, float scale)
{
    extern __shared__ __align__(16) char smem[];
    const uint32_t sbase = smem_u32(smem);
    const int tid = threadIdx.x;
    const int lane = tid & 31;
    const int wid = tid >> 5;
    const int wm = wid & 1;
    const int wn = wid >> 1;

    const int NT = 32;
    int t = blockIdx.x;
    int i = (int)((2.f * NT + 1.f -
                   sqrtf((2.f * NT + 1.f) * (2.f * NT + 1.f) - 8.f * t)) * 0.5f);
    while ((i + 1) * NT - ((i + 1) * i) / 2 <= t) i++;
    while (i * NT - (i * (i - 1)) / 2 > t) i--;
    int j = i + (t - (i * NT - (i * (i - 1)) / 2));
    const size_t Ms = (size_t)i * 128;
    const size_t Ns = (size_t)j * 128;
    const int z = blockIdx.z;
    const __nv_bfloat16* pAh = Ah + (size_t)z * sA + Ms * K;
    const __nv_bfloat16* pAl = Al + (size_t)z * sA + Ms * K;
    const __nv_bfloat16* pBh = Ah + (size_t)z * sA + Ns * K;
    const __nv_bfloat16* pBl = Al + (size_t)z * sA + Ns * K;

    const int KC = K >> 6;
    const int T = 2 * KC;

    float acc[4][4][4];
#pragma unroll
    for (int a = 0; a < 4; a++)
#pragma unroll
        for (int b = 0; b < 4; b++)
#pragma unroll
            for (int k = 0; k < 4; k++) acc[a][b][k] = 0.f;

    auto load_chunk = [&](int tt) {
        const int pass = tt / KC;
        const int kk = (tt - pass * KC) << 6;
        const __nv_bfloat16* pA = (pass == 1) ? pAl : pAh;
        const __nv_bfloat16* pB = pBh;
        const uint32_t st = sbase + (tt % 3) * 32768;
#pragma unroll
        for (int q = 0; q < 4; q++) {
            int idx = q * 256 + tid;
            int row = idx >> 3, c = idx & 7;
            uint32_t sa = st + row * 128 + ((c ^ (row & 7)) << 4);
            cp_async16(sa, pA + (size_t)row * K + kk + c * 8);
        }
#pragma unroll
        for (int q = 0; q < 4; q++) {
            int idx = q * 256 + tid;
            int row = idx >> 3, c = idx & 7;
            uint32_t sa = st + 16384 + row * 128 + ((c ^ (row & 7)) << 4);
            cp_async16(sa, pB + (size_t)row * K + kk + c * 8);
        }
        cp_commit();
    };

    load_chunk(0);
    load_chunk(1);

#pragma unroll 1
    for (int tt = 0; tt < T; tt++) {
        if (tt + 1 < T) cp_wait1(); else cp_wait0();
        __syncthreads();
        if (tt + 2 < T) load_chunk(tt + 2);

        const uint32_t Ab = sbase + (tt % 3) * 32768;
        const uint32_t Bb = Ab + 16384;
#pragma unroll
        for (int ks = 0; ks < 4; ks++) {
            uint32_t afr[4][4];
#pragma unroll
            for (int mt = 0; mt < 4; mt++) {
                int arow = wm * 64 + mt * 16 + (lane & 15);
                int c = ks * 2 + (lane >> 4);
                ldmatrix_x4(afr[mt], Ab + arow * 128 + ((c ^ (arow & 7)) << 4));
            }
            uint32_t bfr[2][4];
#pragma unroll
            for (int np = 0; np < 2; np++) {
                int nrow = wn * 32 + np * 16 + (lane & 7) + ((lane >> 4) << 3);
                int c = ks * 2 + ((lane >> 3) & 1);
                ldmatrix_x4(bfr[np], Bb + nrow * 128 + ((c ^ (nrow & 7)) << 4));
            }
#pragma unroll
            for (int mt = 0; mt < 4; mt++)
#pragma unroll
                for (int nt = 0; nt < 4; nt++)
                    mma_bf16(acc[mt][nt], afr[mt],
                             bfr[nt >> 1][(nt & 1) * 2],
                             bfr[nt >> 1][(nt & 1) * 2 + 1]);
        }
    }

    __nv_bfloat16* stg = (__nv_bfloat16*)smem;     // [128][136]
    __syncthreads();

    const int tg = lane >> 2, tq = lane & 3;
    __nv_bfloat16* pC = C0 + (size_t)z * sC + Ms * ldc + Ns;
#pragma unroll
    for (int mt = 0; mt < 4; mt++) {
#pragma unroll
        for (int nt = 0; nt < 4; nt++) {
            int r0 = wm * 64 + mt * 16 + tg;
            int cc = wn * 32 + nt * 8 + tq * 2;
            __nv_bfloat16 h00 = __float2bfloat16(acc[mt][nt][0] * scale);
            __nv_bfloat16 h01 = __float2bfloat16(acc[mt][nt][1] * scale);
            __nv_bfloat16 h10 = __float2bfloat16(acc[mt][nt][2] * scale);
            __nv_bfloat16 h11 = __float2bfloat16(acc[mt][nt][3] * scale);
            *(__nv_bfloat162*)(pC + (size_t)r0 * ldc + cc) = __nv_bfloat162(h00, h01);
            *(__nv_bfloat162*)(pC + (size_t)(r0 + 8) * ldc + cc) = __nv_bfloat162(h10, h11);
            stg[r0 * 136 + cc]           = h00;
            stg[r0 * 136 + cc + 1]       = h01;
            stg[(r0 + 8) * 136 + cc]     = h10;
            stg[(r0 + 8) * 136 + cc + 1] = h11;
        }
    }

    if (i != j) {
        __syncthreads();
        __nv_bfloat16* pT = C0 + (size_t)z * sC + Ns * ldc + Ms;
        const int orow = tid >> 1;
        const int half = tid & 1;
#pragma unroll
        for (int q = 0; q < 8; q++) {
            int c0 = half * 64 + q * 8;
            __nv_bfloat16 tmp[8];
#pragma unroll
            for (int e = 0; e < 8; e++)
                tmp[e] = stg[(c0 + e) * 136 + orow];
            *(uint4*)(pT + (size_t)orow * ldc + c0) = *(uint4*)tmp;
        }
    }
}

// ---------------------------------------------------------------------------
// WIDE GEMM: CTA tile 128x256, 8 warps (2m x 4n), warp 64x64, K-chunk 64.
// NPASS=3: AhBh + AlBh + AhBl.
// OMODE=0: fp32 out (+bias). OMODE=2: bf16 hi/lo out (+bias).
// Smem: 3 stages x (A 16KB + B 32KB) = 144KB. Depth-2 cp.async prefetch.
// ---------------------------------------------------------------------------
#define WGEMM_SMEM (3 * 49152)

template <int OMODE>
__global__ __launch_bounds__(256)
void gemm_wide(const __nv_bfloat16* __restrict__ Ah, const __nv_bfloat16* __restrict__ Al,
               const __nv_bfloat16* __restrict__ Bh, const __nv_bfloat16* __restrict__ Bl,
               void* __restrict__ C0p, void* __restrict__ C1p,
               const float* __restrict__ bias, int K, int ldc,
               long long sA, long long sB, long long sC, float scale)
{
    extern __shared__ __align__(16) char smem[];
    const uint32_t sbase = smem_u32(smem);
    const int tid = threadIdx.x;
    const int lane = tid & 31;
    const int wid = tid >> 5;
    const int wm = wid & 1;        // 2 warp rows (64 rows each)
    const int wn = wid >> 1;       // 4 warp cols (64 cols each)

    const size_t Ms = (size_t)blockIdx.y * 128;
    const size_t Ns = (size_t)blockIdx.x * 256;
    const int z = blockIdx.z;
    const __nv_bfloat16* pAh = Ah + (size_t)z * sA + Ms * K;
    const __nv_bfloat16* pAl = Al + (size_t)z * sA + Ms * K;
    const __nv_bfloat16* pBh = Bh + (size_t)z * sB + Ns * K;
    const __nv_bfloat16* pBl = Bl + (size_t)z * sB + Ns * K;

    const int KC = K >> 6;
    const int T = 3 * KC;

    float acc[4][8][4];
#pragma unroll
    for (int a = 0; a < 4; a++)
#pragma unroll
        for (int b = 0; b < 8; b++)
#pragma unroll
            for (int k = 0; k < 4; k++) acc[a][b][k] = 0.f;

    auto load_chunk = [&](int t) {
        const int pass = t / KC;
        const int kk = (t - pass * KC) << 6;
        const __nv_bfloat16* pA = (pass == 1) ? pAl : pAh;
        const __nv_bfloat16* pB = (pass == 2) ? pBl : pBh;
        const uint32_t st = sbase + (t % 3) * 49152;
#pragma unroll
        for (int q = 0; q < 4; q++) {           // A: 128 rows x 128B
            int idx = q * 256 + tid;
            int row = idx >> 3, c = idx & 7;
            uint32_t sa = st + row * 128 + ((c ^ (row & 7)) << 4);
            cp_async16(sa, pA + (size_t)row * K + kk + c * 8);
        }
#pragma unroll
        for (int q = 0; q < 8; q++) {           // B: 256 rows x 128B
            int idx = q * 256 + tid;
            int row = idx >> 3, c = idx & 7;
            uint32_t sa = st + 16384 + row * 128 + ((c ^ (row & 7)) << 4);
            cp_async16(sa, pB + (size_t)row * K + kk + c * 8);
        }
        cp_commit();
    };

    load_chunk(0);
    load_chunk(1);

#pragma unroll 1
    for (int t = 0; t < T; t++) {
        if (t + 1 < T) cp_wait1(); else cp_wait0();
        __syncthreads();
        if (t + 2 < T) load_chunk(t + 2);

        const uint32_t Ab = sbase + (t % 3) * 49152;
        const uint32_t Bb = Ab + 16384;
#pragma unroll
        for (int ks = 0; ks < 4; ks++) {
            uint32_t afr[4][4];
#pragma unroll
            for (int mt = 0; mt < 4; mt++) {
                int arow = wm * 64 + mt * 16 + (lane & 15);
                int c = ks * 2 + (lane >> 4);
                ldmatrix_x4(afr[mt], Ab + arow * 128 + ((c ^ (arow & 7)) << 4));
            }
            uint32_t bfr[4][4];
#pragma unroll
            for (int np = 0; np < 4; np++) {
                int nrow = wn * 64 + np * 16 + (lane & 7) + ((lane >> 4) << 3);
                int c = ks * 2 + ((lane >> 3) & 1);
                ldmatrix_x4(bfr[np], Bb + nrow * 128 + ((c ^ (nrow & 7)) << 4));
            }
#pragma unroll
            for (int mt = 0; mt < 4; mt++)
#pragma unroll
                for (int nt = 0; nt < 8; nt++)
                    mma_bf16(acc[mt][nt], afr[mt],
                             bfr[nt >> 1][(nt & 1) * 2],
                             bfr[nt >> 1][(nt & 1) * 2 + 1]);
        }
    }

    // epilogue
    const int tg = lane >> 2, tq = lane & 3;
#pragma unroll
    for (int mt = 0; mt < 4; mt++) {
#pragma unroll
        for (int nt = 0; nt < 8; nt++) {
            int r0 = wm * 64 + mt * 16 + tg;
            int cc = wn * 64 + nt * 8 + tq * 2;
            float b0 = 0.f, b1 = 0.f;
            if (bias) { b0 = bias[Ns + cc]; b1 = bias[Ns + cc + 1]; }
            float v00 = acc[mt][nt][0] * scale + b0;
            float v01 = acc[mt][nt][1] * scale + b1;
            float v10 = acc[mt][nt][2] * scale + b0;
            float v11 = acc[mt][nt][3] * scale + b1;
            if (OMODE == 0) {
                float* pC = (float*)C0p + (size_t)z * sC + Ms * ldc + Ns;
                float2 w0 = { v00, v01 }, w1 = { v10, v11 };
                *(float2*)(pC + (size_t)r0 * ldc + cc)       = w0;
                *(float2*)(pC + (size_t)(r0 + 8) * ldc + cc) = w1;
            } else {
                __nv_bfloat16* pH = (__nv_bfloat16*)C0p + (size_t)z * sC + Ms * ldc + Ns;
                __nv_bfloat16* pL = (__nv_bfloat16*)C1p + (size_t)z * sC + Ms * ldc + Ns;
                __nv_bfloat16 h00 = __float2bfloat16(v00), h01 = __float2bfloat16(v01);
                __nv_bfloat16 h10 = __float2bfloat16(v10), h11 = __float2bfloat16(v11);
                *(__nv_bfloat162*)(pH + (size_t)r0 * ldc + cc) = __nv_bfloat162(h00, h01);
                *(__nv_bfloat162*)(pH + (size_t)(r0 + 8) * ldc + cc) = __nv_bfloat162(h10, h11);
                *(__nv_bfloat162*)(pL + (size_t)r0 * ldc + cc) =
                    __nv_bfloat162(__float2bfloat16(v00 - __bfloat162float(h00)),
                                   __float2bfloat16(v01 - __bfloat162float(h01)));
                *(__nv_bfloat162*)(pL + (size_t)(r0 + 8) * ldc + cc) =
                    __nv_bfloat162(__float2bfloat16(v10 - __bfloat162float(h10)),
                                   __float2bfloat16(v11 - __bfloat162float(h11)));
            }
        }
    }
}

// ---------------------------------------------------------------------------
// fp32 -> (bf16 hi, bf16 lo) split, 4 elements/thread
// ---------------------------------------------------------------------------
__global__ __launch_bounds__(256)
void conv_split(const float* __restrict__ in, __nv_bfloat16* __restrict__ hi,
                __nv_bfloat16* __restrict__ lo, int n)
{
    int i = (blockIdx.x * 256 + threadIdx.x) * 4;
    if (i >= n) return;
    float4 v = *(const float4*)(in + i);
    __nv_bfloat16 h0 = __float2bfloat16(v.x), h1 = __float2bfloat16(v.y);
    __nv_bfloat16 h2 = __float2bfloat16(v.z), h3 = __float2bfloat16(v.w);
    __nv_bfloat162 ph0(h0, h1), ph1(h2, h3);
    __nv_bfloat162 pl0(__float2bfloat16(v.x - __bfloat162float(h0)),
                       __float2bfloat16(v.y - __bfloat162float(h1)));
    __nv_bfloat162 pl1(__float2bfloat16(v.z - __bfloat162float(h2)),
                       __float2bfloat16(v.w - __bfloat162float(h3)));
    *(__nv_bfloat162*)(hi + i)     = ph0;
    *(__nv_bfloat162*)(hi + i + 2) = ph1;
    *(__nv_bfloat162*)(lo + i)     = pl0;
    *(__nv_bfloat162*)(lo + i + 2) = pl1;
}

// ---------------------------------------------------------------------------
// transpose + split: in [R][C] fp32 -> out [C][R] bf16 hi/lo. block (32,8)
// ---------------------------------------------------------------------------
__global__ __launch_bounds__(256)
void transpose_split(const float* __restrict__ in, __nv_bfloat16* __restrict__ oh,
                     __nv_bfloat16* __restrict__ ol, int R, int C,
                     long long sIn, long long sOut)
{
    __shared__ float tile[32][33];
    const int c0 = blockIdx.x * 32, r0 = blockIdx.y * 32, z = blockIdx.z;
    in += (size_t)z * sIn; oh += (size_t)z * sOut; ol += (size_t)z * sOut;
    const int tx = threadIdx.x, ty = threadIdx.y;
#pragma unroll
    for (int j = 0; j < 4; j++)
        tile[ty + 8 * j][tx] = in[(size_t)(r0 + ty + 8 * j) * C + c0 + tx];
    __syncthreads();
#pragma unroll
    for (int j = 0; j < 4; j++) {
        float v = tile[tx][ty + 8 * j];
        __nv_bfloat16 h = __float2bfloat16(v);
        size_t o = (size_t)(c0 + ty + 8 * j) * R + r0 + tx;
        oh[o] = h;
        ol[o] = __float2bfloat16(v - __bfloat162float(h));
    }
}

// ---------------------------------------------------------------------------
// Row softmax on bf16 S -> bf16 hi/lo P. grid (4096, 1, B), 256 threads.
// ---------------------------------------------------------------------------
__global__ __launch_bounds__(256)
void softmax_split_b(const __nv_bfloat16* __restrict__ S,
                     __nv_bfloat16* __restrict__ Ph, __nv_bfloat16* __restrict__ Pl)
{
    const size_t row = (size_t)blockIdx.z * N_ + blockIdx.x;
    const uint4* r4 = (const uint4*)(S + row * N_);
    uint4* ph4 = (uint4*)(Ph + row * N_);
    uint4* pl4 = (uint4*)(Pl + row * N_);
    const int tid = threadIdx.x, lane = tid & 31, wid = tid >> 5;
    __shared__ float red[8];
    __shared__ float bval;

    uint4 u[2];
    u[0] = r4[tid];
    u[1] = r4[tid + 256];
    float v[16];
#pragma unroll
    for (int q = 0; q < 2; q++) {
        const uint32_t* w = (const uint32_t*)&u[q];
#pragma unroll
        for (int j = 0; j < 4; j++) {
            float2 f = __bfloat1622float2(*(const __nv_bfloat162*)&w[j]);
            v[q * 8 + j * 2]     = f.x;
            v[q * 8 + j * 2 + 1] = f.y;
        }
    }

    float mx = v[0];
#pragma unroll
    for (int j = 1; j < 16; j++) mx = fmaxf(mx, v[j]);
#pragma unroll
    for (int off = 16; off; off >>= 1)
        mx = fmaxf(mx, __shfl_xor_sync(0xffffffffu, mx, off));
    if (lane == 0) red[wid] = mx;
    __syncthreads();
    if (tid == 0) {
        float m = red[0];
#pragma unroll
        for (int i = 1; i < 8; i++) m = fmaxf(m, red[i]);
        bval = m;
    }
    __syncthreads();
    mx = bval;

    float s = 0.f;
#pragma unroll
    for (int j = 0; j < 16; j++) { v[j] = __expf(v[j] - mx); s += v[j]; }
#pragma unroll
    for (int off = 16; off; off >>= 1)
        s += __shfl_xor_sync(0xffffffffu, s, off);
    if (lane == 0) red[wid] = s;
    __syncthreads();
    if (tid == 0) {
        float t = 0.f;
#pragma unroll
        for (int i = 0; i < 8; i++) t += red[i];
        bval = 1.f / t;
    }
    __syncthreads();
    const float inv = bval;

    uint4 oh[2], ol[2];
#pragma unroll
    for (int q = 0; q < 2; q++) {
        uint32_t* wh = (uint32_t*)&oh[q];
        uint32_t* wl = (uint32_t*)&ol[q];
#pragma unroll
        for (int j = 0; j < 4; j++) {
            float a = v[q * 8 + j * 2] * inv;
            float b = v[q * 8 + j * 2 + 1] * inv;
            __nv_bfloat16 ha = __float2bfloat16(a), hb = __float2bfloat16(b);
            __nv_bfloat162 hp(ha, hb);
            __nv_bfloat162 lp(__float2bfloat16(a - __bfloat162float(ha)),
                              __float2bfloat16(b - __bfloat162float(hb)));
            wh[j] = *(uint32_t*)&hp;
            wl[j] = *(uint32_t*)&lp;
        }
    }
    ph4[tid]       = oh[0];
    ph4[tid + 256] = oh[1];
    pl4[tid]       = ol[0];
    pl4[tid + 256] = ol[1];
}

// ---------------------------------------------------------------------------
// Hyperedge branch
// ---------------------------------------------------------------------------
__global__ __launch_bounds__(256)
void edge_mean_kernel(const float* __restrict__ x, const int* __restrict__ Hm)
{
    const int e = blockIdx.x, b = blockIdx.y, f = threadIdx.x;
    const float* xb = x + (size_t)b * N_ * F_;
    float sum = 0.f;
    int cnt = 0;
    for (int n = 0; n < N_; n++) {
        if (Hm[(size_t)n * E_ + e]) {
            sum += xb[(size_t)n * F_ + f];
            cnt++;
        }
    }
    const float deg = (float)cnt;
    g_mean[((size_t)b * MAXE + e) * F_ + f] = sum / fmaxf(deg, 1.0f);
    if (f == 0 && b == 0) g_deg[e] = deg;
}

__global__ __launch_bounds__(128)
void ctx_kernel(const float* __restrict__ m1w, const float* __restrict__ m1b,
                const float* __restrict__ m2w, const float* __restrict__ m2b,
                const float* __restrict__ m3w, const float* __restrict__ m3b)
{
    const int e = blockIdx.x, b = blockIdx.y, t = threadIdx.x;
    __shared__ float ms[F_];
    __shared__ float h1[H1_];
    __shared__ float h2[H2_];
    __shared__ float red[4];

    const float* mp = g_mean + ((size_t)b * MAXE + e) * F_;
    ms[t]       = mp[t];
    ms[t + 128] = mp[t + 128];
    __syncthreads();

    float s = m1b[t];
    for (int k = 0; k < F_; k++) s += ms[k] * m1w[k * H1_ + t];
    h1[t] = fmaxf(s, 0.f);
    __syncthreads();

    if (t < H2_) {
        float s2 = m2b[t];
        for (int k = 0; k < H1_; k++) s2 += h1[k] * m2w[k * H2_ + t];
        h2[t] = fmaxf(s2, 0.f);
    }
    __syncthreads();

    float p = (t < H2_) ? h2[t] * m3w[t] : 0.f;
#pragma unroll
    for (int off = 16; off; off >>= 1)
        p += __shfl_xor_sync(0xffffffffu, p, off);
    if ((t & 31) == 0) red[t >> 5] = p;
    __syncthreads();
    if (t == 0)
        g_ctx[b * MAXE + e] = red[0] + red[1] + red[2] + red[3] + m3b[0];
}

__global__ __launch_bounds__(256)
void aw_kernel(const float* __restrict__ x, const int* __restrict__ Hm,
               const float* __restrict__ cw, const float* __restrict__ cb,
               const float* __restrict__ hb, const float* __restrict__ alpha,
               float* __restrict__ out)
{
    const int n = blockIdx.x, b = blockIdx.y, t = threadIdx.x;
    __shared__ float red[8];
    __shared__ float compat_s;

    float p = x[((size_t)b * N_ + n) * F_ + t] * cw[t];
#pragma unroll
    for (int off = 16; off; off >>= 1)
        p += __shfl_xor_sync(0xffffffffu, p, off);
    if ((t & 31) == 0) red[t >> 5] = p;
    __syncthreads();
    if (t == 0) {
        float s = 0.f;
#pragma unroll
        for (int i = 0; i < 8; i++) s += red[i];
        compat_s = s + cb[0] + hb[0];
    }
    __syncthreads();

    float val = 0.f;
    if (t < MAXE) {
        if (Hm[(size_t)n * E_ + t] && g_deg[t] > 1.0f) {
            float z = compat_s + alpha[0] * g_ctx[b * MAXE + t];
            val = 1.f / (1.f + __expf(-z));
        }
    }
    out[((size_t)b * N_ + n) * OUTC + t] = val;
}

// ---------------------------------------------------------------------------
// Launch
// ---------------------------------------------------------------------------
extern "C" void kernel_launch(void* const* d_in, const int* in_sizes, int n_in,
                              void* d_out, int out_size)
{
    const float* x      = (const float*)d_in[0];
    const int*   Hm     = (const int*)  d_in[1];
    const float* weight = (const float*)d_in[2];
    const float* bias   = (const float*)d_in[3];
    const float* Wn_w   = (const float*)d_in[4];
    const float* Wn_b   = (const float*)d_in[5];
    const float* m1_w   = (const float*)d_in[6];
    const float* m1_b   = (const float*)d_in[7];
    const float* m2_w   = (const float*)d_in[8];
    const float* m2_b   = (const float*)d_in[9];
    const float* m3_w   = (const float*)d_in[10];
    const float* m3_b   = (const float*)d_in[11];
    const float* c_w    = (const float*)d_in[12];
    const float* c_b    = (const float*)d_in[13];
    const float* hedgeb = (const float*)d_in[14];
    const float* alpha  = (const float*)d_in[15];
    float* out = (float*)d_out;

    float* v;
    __nv_bfloat16 *Sb, *xh, *xl, *xph, *xpl, *vth, *vtl, *Ph, *Pl;
    __nv_bfloat16 *wth, *wtl, *wnth, *wntl;
    cudaGetSymbolAddress((void**)&v,   g_v);
    cudaGetSymbolAddress((void**)&Sb,  g_Sb);
    cudaGetSymbolAddress((void**)&xh,  g_xh);
    cudaGetSymbolAddress((void**)&xl,  g_xl);
    cudaGetSymbolAddress((void**)&xph, g_xph);
    cudaGetSymbolAddress((void**)&xpl, g_xpl);
    cudaGetSymbolAddress((void**)&vth, g_vth);
    cudaGetSymbolAddress((void**)&vtl, g_vtl);
    cudaGetSymbolAddress((void**)&Ph,  g_Ph);
    cudaGetSymbolAddress((void**)&Pl,  g_Pl);
    cudaGetSymbolAddress((void**)&wth, g_wth);
    cudaGetSymbolAddress((void**)&wtl, g_wtl);
    cudaGetSymbolAddress((void**)&wnth, g_wnth);
    cudaGetSymbolAddress((void**)&wntl, g_wntl);

    cudaFuncSetAttribute(gemm_sym,
                         cudaFuncAttributeMaxDynamicSharedMemorySize, GEMM_SMEM);
    cudaFuncSetAttribute(gemm_wide<0>,
                         cudaFuncAttributeMaxDynamicSharedMemorySize, WGEMM_SMEM);
    cudaFuncSetAttribute(gemm_wide<2>,
                         cudaFuncAttributeMaxDynamicSharedMemorySize, WGEMM_SMEM);

    const int nx = B_ * N_ * F_;   // 4M elements

    // hyperedge branch (independent)
    edge_mean_kernel<<<dim3(MAXE, B_), 256>>>(x, Hm);
    ctx_kernel<<<dim3(MAXE, B_), 128>>>(m1_w, m1_b, m2_w, m2_b, m3_w, m3_b);
    aw_kernel<<<dim3(N_, B_), 256>>>(x, Hm, c_w, c_b, hedgeb, alpha, out);

    // input conversions
    conv_split<<<nx / 4 / 256, 256>>>(x, xh, xl, nx);
    transpose_split<<<dim3(8, 8, 1), dim3(32, 8)>>>(weight, wth, wtl, F_, F_, 0, 0);
    transpose_split<<<dim3(8, 8, 1), dim3(32, 8)>>>(Wn_w, wnth, wntl, F_, F_, 0, 0);

    // projections: xp = x@Wn_w + Wn_b (split emitted) ; v = x@weight (fp32)
    gemm_wide<2><<<dim3(1, (B_ * N_) / 128, 1), 256, WGEMM_SMEM>>>(
        xh, xl, wnth, wntl, xph, xpl, Wn_b, F_, F_, 0, 0, 0, 1.0f);
    gemm_wide<0><<<dim3(1, (B_ * N_) / 128, 1), 256, WGEMM_SMEM>>>(
        xh, xl, wth, wtl, v, nullptr, nullptr, F_, F_, 0, 0, 0, 1.0f);

    // v transposed per batch -> bf16 hi/lo
    transpose_split<<<dim3(F_ / 32, N_ / 32, B_), dim3(32, 8)>>>(
        v, vth, vtl, N_, F_, (long long)N_ * F_, (long long)F_ * N_);

    // S = xp @ xp^T / 16 -> bf16, symmetric: 528 upper-triangle tiles + mirror
    gemm_sym<<<dim3(528, 1, B_), 256, GEMM_SMEM>>>(
        xph, xpl, Sb, F_, N_,
        (long long)N_ * F_, (long long)N_ * N_, 0.0625f);

    // P = softmax(S) -> bf16 hi/lo
    softmax_split_b<<<dim3(N_, 1, B_), 256>>>(Sb, Ph, Pl);

    // y = P @ V + bias -> out[..., E:E+F]
    gemm_wide<0><<<dim3(1, N_ / 128, B_), 256, WGEMM_SMEM>>>(
        Ph, Pl, vth, vtl, out + E_, nullptr, bias, N_, OUTC,
        (long long)N_ * N_, (long long)F_ * N_, (long long)N_ * OUTC, 1.0f);
}

// round 12
// speedup vs baseline: 1.0023x; 1.0023x over previous
#include <cuda_runtime.h>
#include <cuda_bf16.h>
#include <cstdint>
#include <cstddef>

// Problem constants
#define B_   4
#define N_   4096
#define E_   256
#define F_   256
#define MAXE 50
#define H1_  128
#define H2_  64
#define OUTC 512

// ---------------------------------------------------------------------------
// Static device scratch
// ---------------------------------------------------------------------------
__device__ float g_v [B_ * N_ * F_];                 // v fp32 (16 MB)
__device__ __nv_bfloat16 g_Sb[67108864];             // scores bf16 (128 MB)
__device__ __nv_bfloat16 g_xh [B_ * N_ * F_];        // x hi
__device__ __nv_bfloat16 g_xl [B_ * N_ * F_];        // x lo
__device__ __nv_bfloat16 g_xph[B_ * N_ * F_];        // xp hi
__device__ __nv_bfloat16 g_xpl[B_ * N_ * F_];
__device__ __nv_bfloat16 g_vth[B_ * F_ * N_];        // v^T hi  [b][256][4096]
__device__ __nv_bfloat16 g_vtl[B_ * F_ * N_];
__device__ __nv_bfloat16 g_Ph [67108864];            // softmax(S) hi (128 MB)
__device__ __nv_bfloat16 g_Pl [67108864];            // softmax(S) lo (128 MB)
__device__ __nv_bfloat16 g_wth [F_ * F_], g_wtl [F_ * F_];   // weight^T hi/lo
__device__ __nv_bfloat16 g_wnth[F_ * F_], g_wntl[F_ * F_];   // Wn_w^T hi/lo
__device__ float g_mean[B_ * MAXE * F_];
__device__ float g_ctx [B_ * MAXE];
__device__ float g_deg [MAXE];

// ---------------------------------------------------------------------------
// PTX helpers (base sm_100-safe: mma.sync / ldmatrix / cp.async)
// ---------------------------------------------------------------------------
__device__ __forceinline__ uint32_t smem_u32(const void* p) {
    uint32_t a;
    asm("{ .reg .u64 t; cvta.to.shared.u64 t, %1; cvt.u32.u64 %0, t; }"
        : "=r"(a) : "l"(p));
    return a;
}
__device__ __forceinline__ void cp_async16(uint32_t s, const void* g) {
    asm volatile("cp.async.cg.shared.global [%0], [%1], 16;\n"
        :: "r"(s), "l"((unsigned long long)__cvta_generic_to_global(g)) : "memory");
}
__device__ __forceinline__ void cp_commit() {
    asm volatile("cp.async.commit_group;\n" ::: "memory");
}
__device__ __forceinline__ void cp_wait0() {
    asm volatile("cp.async.wait_group 0;\n" ::: "memory");
}
__device__ __forceinline__ void cp_wait1() {
    asm volatile("cp.async.wait_group 1;\n" ::: "memory");
}
__device__ __forceinline__ void ldmatrix_x4(uint32_t* r, uint32_t addr) {
    asm volatile("ldmatrix.sync.aligned.m8n8.x4.shared.b16 {%0,%1,%2,%3}, [%4];\n"
        : "=r"(r[0]), "=r"(r[1]), "=r"(r[2]), "=r"(r[3]) : "r"(addr));
}
__device__ __forceinline__ void mma_bf16(float* d, const uint32_t* a,
                                         uint32_t b0, uint32_t b1) {
    asm volatile(
        "mma.sync.aligned.m16n8k16.row.col.f32.bf16.bf16.f32 "
        "{%0,%1,%2,%3}, {%4,%5,%6,%7}, {%8,%9}, {%0,%1,%2,%3};\n"
        : "+f"(d[0]), "+f"(d[1]), "+f"(d[2]), "+f"(d[3])
        : "r"(a[0]), "r"(a[1]), "r"(a[2]), "r"(a[3]), "r"(b0), "r"(b1));
}

// ---------------------------------------------------------------------------
// 128x128 SYM GEMM (S-GEMM only) — unchanged working version.
// NPASS=2: AhBh + AlBh. bf16 out + mirrored transpose tile (symmetric S).
// ---------------------------------------------------------------------------
#define GEMM_SMEM (3 * 32768)

__global__ __launch_bounds__(256)
void gemm_sym(const __nv_bfloat16* __restrict__ Ah, const __nv_bfloat16* __restrict__ Al,
              __nv_bfloat16* __restrict__ C0, int K, int ldc,
              long long sA, long long sC, float scale)
{
    extern __shared__ __align__(16) char smem[];
    const uint32_t sbase = smem_u32(smem);
    const int tid = threadIdx.x;
    const int lane = tid & 31;
    const int wid = tid >> 5;
    const int wm = wid & 1;
    const int wn = wid >> 1;

    const int NT = 32;
    int t = blockIdx.x;
    int i = (int)((2.f * NT + 1.f -
                   sqrtf((2.f * NT + 1.f) * (2.f * NT + 1.f) - 8.f * t)) * 0.5f);
    while ((i + 1) * NT - ((i + 1) * i) / 2 <= t) i++;
    while (i * NT - (i * (i - 1)) / 2 > t) i--;
    int j = i + (t - (i * NT - (i * (i - 1)) / 2));
    const size_t Ms = (size_t)i * 128;
    const size_t Ns = (size_t)j * 128;
    const int z = blockIdx.z;
    const __nv_bfloat16* pAh = Ah + (size_t)z * sA + Ms * K;
    const __nv_bfloat16* pAl = Al + (size_t)z * sA + Ms * K;
    const __nv_bfloat16* pBh = Ah + (size_t)z * sA + Ns * K;
    const __nv_bfloat16* pBl = Al + (size_t)z * sA + Ns * K;

    const int KC = K >> 6;
    const int T = 2 * KC;

    float acc[4][4][4];
#pragma unroll
    for (int a = 0; a < 4; a++)
#pragma unroll
        for (int b = 0; b < 4; b++)
#pragma unroll
            for (int k = 0; k < 4; k++) acc[a][b][k] = 0.f;

    auto load_chunk = [&](int tt) {
        const int pass = tt / KC;
        const int kk = (tt - pass * KC) << 6;
        const __nv_bfloat16* pA = (pass == 1) ? pAl : pAh;
        const __nv_bfloat16* pB = pBh;
        const uint32_t st = sbase + (tt % 3) * 32768;
#pragma unroll
        for (int q = 0; q < 4; q++) {
            int idx = q * 256 + tid;
            int row = idx >> 3, c = idx & 7;
            uint32_t sa = st + row * 128 + ((c ^ (row & 7)) << 4);
            cp_async16(sa, pA + (size_t)row * K + kk + c * 8);
        }
#pragma unroll
        for (int q = 0; q < 4; q++) {
            int idx = q * 256 + tid;
            int row = idx >> 3, c = idx & 7;
            uint32_t sa = st + 16384 + row * 128 + ((c ^ (row & 7)) << 4);
            cp_async16(sa, pB + (size_t)row * K + kk + c * 8);
        }
        cp_commit();
    };

    load_chunk(0);
    load_chunk(1);

#pragma unroll 1
    for (int tt = 0; tt < T; tt++) {
        if (tt + 1 < T) cp_wait1(); else cp_wait0();
        __syncthreads();
        if (tt + 2 < T) load_chunk(tt + 2);

        const uint32_t Ab = sbase + (tt % 3) * 32768;
        const uint32_t Bb = Ab + 16384;
#pragma unroll
        for (int ks = 0; ks < 4; ks++) {
            uint32_t afr[4][4];
#pragma unroll
            for (int mt = 0; mt < 4; mt++) {
                int arow = wm * 64 + mt * 16 + (lane & 15);
                int c = ks * 2 + (lane >> 4);
                ldmatrix_x4(afr[mt], Ab + arow * 128 + ((c ^ (arow & 7)) << 4));
            }
            uint32_t bfr[2][4];
#pragma unroll
            for (int np = 0; np < 2; np++) {
                int nrow = wn * 32 + np * 16 + (lane & 7) + ((lane >> 4) << 3);
                int c = ks * 2 + ((lane >> 3) & 1);
                ldmatrix_x4(bfr[np], Bb + nrow * 128 + ((c ^ (nrow & 7)) << 4));
            }
#pragma unroll
            for (int mt = 0; mt < 4; mt++)
#pragma unroll
                for (int nt = 0; nt < 4; nt++)
                    mma_bf16(acc[mt][nt], afr[mt],
                             bfr[nt >> 1][(nt & 1) * 2],
                             bfr[nt >> 1][(nt & 1) * 2 + 1]);
        }
    }

    __nv_bfloat16* stg = (__nv_bfloat16*)smem;     // [128][136]
    __syncthreads();

    const int tg = lane >> 2, tq = lane & 3;
    __nv_bfloat16* pC = C0 + (size_t)z * sC + Ms * ldc + Ns;
#pragma unroll
    for (int mt = 0; mt < 4; mt++) {
#pragma unroll
        for (int nt = 0; nt < 4; nt++) {
            int r0 = wm * 64 + mt * 16 + tg;
            int cc = wn * 32 + nt * 8 + tq * 2;
            __nv_bfloat16 h00 = __float2bfloat16(acc[mt][nt][0] * scale);
            __nv_bfloat16 h01 = __float2bfloat16(acc[mt][nt][1] * scale);
            __nv_bfloat16 h10 = __float2bfloat16(acc[mt][nt][2] * scale);
            __nv_bfloat16 h11 = __float2bfloat16(acc[mt][nt][3] * scale);
            *(__nv_bfloat162*)(pC + (size_t)r0 * ldc + cc) = __nv_bfloat162(h00, h01);
            *(__nv_bfloat162*)(pC + (size_t)(r0 + 8) * ldc + cc) = __nv_bfloat162(h10, h11);
            stg[r0 * 136 + cc]           = h00;
            stg[r0 * 136 + cc + 1]       = h01;
            stg[(r0 + 8) * 136 + cc]     = h10;
            stg[(r0 + 8) * 136 + cc + 1] = h11;
        }
    }

    if (i != j) {
        __syncthreads();
        __nv_bfloat16* pT = C0 + (size_t)z * sC + Ns * ldc + Ms;
        const int orow = tid >> 1;
        const int half = tid & 1;
#pragma unroll
        for (int q = 0; q < 8; q++) {
            int c0 = half * 64 + q * 8;
            __nv_bfloat16 tmp[8];
#pragma unroll
            for (int e = 0; e < 8; e++)
                tmp[e] = stg[(c0 + e) * 136 + orow];
            *(uint4*)(pT + (size_t)orow * ldc + c0) = *(uint4*)tmp;
        }
    }
}

// ---------------------------------------------------------------------------
// WIDE GEMM: CTA tile 128x256, 8 warps (2m x 4n), warp 64x64, K-chunk 64.
// NPASS=3: AhBh + AlBh + AhBl.
// OMODE=0: fp32 out (+bias). OMODE=2: bf16 hi/lo out (+bias).
// Smem: 3 stages x (A 16KB + B 32KB) = 144KB. Depth-2 cp.async prefetch.
// ---------------------------------------------------------------------------
#define WGEMM_SMEM (3 * 49152)

template <int OMODE>
__global__ __launch_bounds__(256)
void gemm_wide(const __nv_bfloat16* __restrict__ Ah, const __nv_bfloat16* __restrict__ Al,
               const __nv_bfloat16* __restrict__ Bh, const __nv_bfloat16* __restrict__ Bl,
               void* __restrict__ C0p, void* __restrict__ C1p,
               const float* __restrict__ bias, int K, int ldc,
               long long sA, long long sB, long long sC, float scale)
{
    extern __shared__ __align__(16) char smem[];
    const uint32_t sbase = smem_u32(smem);
    const int tid = threadIdx.x;
    const int lane = tid & 31;
    const int wid = tid >> 5;
    const int wm = wid & 1;        // 2 warp rows (64 rows each)
    const int wn = wid >> 1;       // 4 warp cols (64 cols each)

    const size_t Ms = (size_t)blockIdx.y * 128;
    const size_t Ns = (size_t)blockIdx.x * 256;
    const int z = blockIdx.z;
    const __nv_bfloat16* pAh = Ah + (size_t)z * sA + Ms * K;
    const __nv_bfloat16* pAl = Al + (size_t)z * sA + Ms * K;
    const __nv_bfloat16* pBh = Bh + (size_t)z * sB + Ns * K;
    const __nv_bfloat16* pBl = Bl + (size_t)z * sB + Ns * K;

    const int KC = K >> 6;
    const int T = 3 * KC;

    float acc[4][8][4];
#pragma unroll
    for (int a = 0; a < 4; a++)
#pragma unroll
        for (int b = 0; b < 8; b++)
#pragma unroll
            for (int k = 0; k < 4; k++) acc[a][b][k] = 0.f;

    auto load_chunk = [&](int t) {
        const int pass = t / KC;
        const int kk = (t - pass * KC) << 6;
        const __nv_bfloat16* pA = (pass == 1) ? pAl : pAh;
        const __nv_bfloat16* pB = (pass == 2) ? pBl : pBh;
        const uint32_t st = sbase + (t % 3) * 49152;
#pragma unroll
        for (int q = 0; q < 4; q++) {           // A: 128 rows x 128B
            int idx = q * 256 + tid;
            int row = idx >> 3, c = idx & 7;
            uint32_t sa = st + row * 128 + ((c ^ (row & 7)) << 4);
            cp_async16(sa, pA + (size_t)row * K + kk + c * 8);
        }
#pragma unroll
        for (int q = 0; q < 8; q++) {           // B: 256 rows x 128B
            int idx = q * 256 + tid;
            int row = idx >> 3, c = idx & 7;
            uint32_t sa = st + 16384 + row * 128 + ((c ^ (row & 7)) << 4);
            cp_async16(sa, pB + (size_t)row * K + kk + c * 8);
        }
        cp_commit();
    };

    load_chunk(0);
    load_chunk(1);

#pragma unroll 1
    for (int t = 0; t < T; t++) {
        if (t + 1 < T) cp_wait1(); else cp_wait0();
        __syncthreads();
        if (t + 2 < T) load_chunk(t + 2);

        const uint32_t Ab = sbase + (t % 3) * 49152;
        const uint32_t Bb = Ab + 16384;
#pragma unroll
        for (int ks = 0; ks < 4; ks++) {
            uint32_t afr[4][4];
#pragma unroll
            for (int mt = 0; mt < 4; mt++) {
                int arow = wm * 64 + mt * 16 + (lane & 15);
                int c = ks * 2 + (lane >> 4);
                ldmatrix_x4(afr[mt], Ab + arow * 128 + ((c ^ (arow & 7)) << 4));
            }
            uint32_t bfr[4][4];
#pragma unroll
            for (int np = 0; np < 4; np++) {
                int nrow = wn * 64 + np * 16 + (lane & 7) + ((lane >> 4) << 3);
                int c = ks * 2 + ((lane >> 3) & 1);
                ldmatrix_x4(bfr[np], Bb + nrow * 128 + ((c ^ (nrow & 7)) << 4));
            }
#pragma unroll
            for (int mt = 0; mt < 4; mt++)
#pragma unroll
                for (int nt = 0; nt < 8; nt++)
                    mma_bf16(acc[mt][nt], afr[mt],
                             bfr[nt >> 1][(nt & 1) * 2],
                             bfr[nt >> 1][(nt & 1) * 2 + 1]);
        }
    }

    // epilogue
    const int tg = lane >> 2, tq = lane & 3;
#pragma unroll
    for (int mt = 0; mt < 4; mt++) {
#pragma unroll
        for (int nt = 0; nt < 8; nt++) {
            int r0 = wm * 64 + mt * 16 + tg;
            int cc = wn * 64 + nt * 8 + tq * 2;
            float b0 = 0.f, b1 = 0.f;
            if (bias) { b0 = bias[Ns + cc]; b1 = bias[Ns + cc + 1]; }
            float v00 = acc[mt][nt][0] * scale + b0;
            float v01 = acc[mt][nt][1] * scale + b1;
            float v10 = acc[mt][nt][2] * scale + b0;
            float v11 = acc[mt][nt][3] * scale + b1;
            if (OMODE == 0) {
                float* pC = (float*)C0p + (size_t)z * sC + Ms * ldc + Ns;
                float2 w0 = { v00, v01 }, w1 = { v10, v11 };
                *(float2*)(pC + (size_t)r0 * ldc + cc)       = w0;
                *(float2*)(pC + (size_t)(r0 + 8) * ldc + cc) = w1;
            } else {
                __nv_bfloat16* pH = (__nv_bfloat16*)C0p + (size_t)z * sC + Ms * ldc + Ns;
                __nv_bfloat16* pL = (__nv_bfloat16*)C1p + (size_t)z * sC + Ms * ldc + Ns;
                __nv_bfloat16 h00 = __float2bfloat16(v00), h01 = __float2bfloat16(v01);
                __nv_bfloat16 h10 = __float2bfloat16(v10), h11 = __float2bfloat16(v11);
                *(__nv_bfloat162*)(pH + (size_t)r0 * ldc + cc) = __nv_bfloat162(h00, h01);
                *(__nv_bfloat162*)(pH + (size_t)(r0 + 8) * ldc + cc) = __nv_bfloat162(h10, h11);
                *(__nv_bfloat162*)(pL + (size_t)r0 * ldc + cc) =
                    __nv_bfloat162(__float2bfloat16(v00 - __bfloat162float(h00)),
                                   __float2bfloat16(v01 - __bfloat162float(h01)));
                *(__nv_bfloat162*)(pL + (size_t)(r0 + 8) * ldc + cc) =
                    __nv_bfloat162(__float2bfloat16(v10 - __bfloat162float(h10)),
                                   __float2bfloat16(v11 - __bfloat162float(h11)));
            }
        }
    }
}

// ---------------------------------------------------------------------------
// fp32 -> (bf16 hi, bf16 lo) split, 4 elements/thread
// ---------------------------------------------------------------------------
__global__ __launch_bounds__(256)
void conv_split(const float* __restrict__ in, __nv_bfloat16* __restrict__ hi,
                __nv_bfloat16* __restrict__ lo, int n)
{
    int i = (blockIdx.x * 256 + threadIdx.x) * 4;
    if (i >= n) return;
    float4 v = *(const float4*)(in + i);
    __nv_bfloat16 h0 = __float2bfloat16(v.x), h1 = __float2bfloat16(v.y);
    __nv_bfloat16 h2 = __float2bfloat16(v.z), h3 = __float2bfloat16(v.w);
    __nv_bfloat162 ph0(h0, h1), ph1(h2, h3);
    __nv_bfloat162 pl0(__float2bfloat16(v.x - __bfloat162float(h0)),
                       __float2bfloat16(v.y - __bfloat162float(h1)));
    __nv_bfloat162 pl1(__float2bfloat16(v.z - __bfloat162float(h2)),
                       __float2bfloat16(v.w - __bfloat162float(h3)));
    *(__nv_bfloat162*)(hi + i)     = ph0;
    *(__nv_bfloat162*)(hi + i + 2) = ph1;
    *(__nv_bfloat162*)(lo + i)     = pl0;
    *(__nv_bfloat162*)(lo + i + 2) = pl1;
}

// ---------------------------------------------------------------------------
// transpose + split: in [R][C] fp32 -> out [C][R] bf16 hi/lo. block (32,8)
// ---------------------------------------------------------------------------
__global__ __launch_bounds__(256)
void transpose_split(const float* __restrict__ in, __nv_bfloat16* __restrict__ oh,
                     __nv_bfloat16* __restrict__ ol, int R, int C,
                     long long sIn, long long sOut)
{
    __shared__ float tile[32][33];
    const int c0 = blockIdx.x * 32, r0 = blockIdx.y * 32, z = blockIdx.z;
    in += (size_t)z * sIn; oh += (size_t)z * sOut; ol += (size_t)z * sOut;
    const int tx = threadIdx.x, ty = threadIdx.y;
#pragma unroll
    for (int j = 0; j < 4; j++)
        tile[ty + 8 * j][tx] = in[(size_t)(r0 + ty + 8 * j) * C + c0 + tx];
    __syncthreads();
#pragma unroll
    for (int j = 0; j < 4; j++) {
        float v = tile[tx][ty + 8 * j];
        __nv_bfloat16 h = __float2bfloat16(v);
        size_t o = (size_t)(c0 + ty + 8 * j) * R + r0 + tx;
        oh[o] = h;
        ol[o] = __float2bfloat16(v - __bfloat162float(h));
    }
}

// ---------------------------------------------------------------------------
// Row softmax on bf16 S -> bf16 hi/lo P. grid (4096, 1, B), 256 threads.
// ---------------------------------------------------------------------------
__global__ __launch_bounds__(256)
void softmax_split_b(const __nv_bfloat16* __restrict__ S,
                     __nv_bfloat16* __restrict__ Ph, __nv_bfloat16* __restrict__ Pl)
{
    const size_t row = (size_t)blockIdx.z * N_ + blockIdx.x;
    const uint4* r4 = (const uint4*)(S + row * N_);
    uint4* ph4 = (uint4*)(Ph + row * N_);
    uint4* pl4 = (uint4*)(Pl + row * N_);
    const int tid = threadIdx.x, lane = tid & 31, wid = tid >> 5;
    __shared__ float red[8];
    __shared__ float bval;

    uint4 u[2];
    u[0] = r4[tid];
    u[1] = r4[tid + 256];
    float v[16];
#pragma unroll
    for (int q = 0; q < 2; q++) {
        const uint32_t* w = (const uint32_t*)&u[q];
#pragma unroll
        for (int j = 0; j < 4; j++) {
            float2 f = __bfloat1622float2(*(const __nv_bfloat162*)&w[j]);
            v[q * 8 + j * 2]     = f.x;
            v[q * 8 + j * 2 + 1] = f.y;
        }
    }

    float mx = v[0];
#pragma unroll
    for (int j = 1; j < 16; j++) mx = fmaxf(mx, v[j]);
#pragma unroll
    for (int off = 16; off; off >>= 1)
        mx = fmaxf(mx, __shfl_xor_sync(0xffffffffu, mx, off));
    if (lane == 0) red[wid] = mx;
    __syncthreads();
    if (tid == 0) {
        float m = red[0];
#pragma unroll
        for (int i = 1; i < 8; i++) m = fmaxf(m, red[i]);
        bval = m;
    }
    __syncthreads();
    mx = bval;

    float s = 0.f;
#pragma unroll
    for (int j = 0; j < 16; j++) { v[j] = __expf(v[j] - mx); s += v[j]; }
#pragma unroll
    for (int off = 16; off; off >>= 1)
        s += __shfl_xor_sync(0xffffffffu, s, off);
    if (lane == 0) red[wid] = s;
    __syncthreads();
    if (tid == 0) {
        float t = 0.f;
#pragma unroll
        for (int i = 0; i < 8; i++) t += red[i];
        bval = 1.f / t;
    }
    __syncthreads();
    const float inv = bval;

    uint4 oh[2], ol[2];
#pragma unroll
    for (int q = 0; q < 2; q++) {
        uint32_t* wh = (uint32_t*)&oh[q];
        uint32_t* wl = (uint32_t*)&ol[q];
#pragma unroll
        for (int j = 0; j < 4; j++) {
            float a = v[q * 8 + j * 2] * inv;
            float b = v[q * 8 + j * 2 + 1] * inv;
            __nv_bfloat16 ha = __float2bfloat16(a), hb = __float2bfloat16(b);
            __nv_bfloat162 hp(ha, hb);
            __nv_bfloat162 lp(__float2bfloat16(a - __bfloat162float(ha)),
                              __float2bfloat16(b - __bfloat162float(hb)));
            wh[j] = *(uint32_t*)&hp;
            wl[j] = *(uint32_t*)&lp;
        }
    }
    ph4[tid]       = oh[0];
    ph4[tid + 256] = oh[1];
    pl4[tid]       = ol[0];
    pl4[tid + 256] = ol[1];
}

// ---------------------------------------------------------------------------
// Hyperedge branch
// ---------------------------------------------------------------------------
__global__ __launch_bounds__(256)
void edge_mean_kernel(const float* __restrict__ x, const int* __restrict__ Hm)
{
    const int e = blockIdx.x, b = blockIdx.y, f = threadIdx.x;
    const float* xb = x + (size_t)b * N_ * F_;
    float sum = 0.f;
    int cnt = 0;
    for (int n = 0; n < N_; n++) {
        if (Hm[(size_t)n * E_ + e]) {
            sum += xb[(size_t)n * F_ + f];
            cnt++;
        }
    }
    const float deg = (float)cnt;
    g_mean[((size_t)b * MAXE + e) * F_ + f] = sum / fmaxf(deg, 1.0f);
    if (f == 0 && b == 0) g_deg[e] = deg;
}

__global__ __launch_bounds__(128)
void ctx_kernel(const float* __restrict__ m1w, const float* __restrict__ m1b,
                const float* __restrict__ m2w, const float* __restrict__ m2b,
                const float* __restrict__ m3w, const float* __restrict__ m3b)
{
    const int e = blockIdx.x, b = blockIdx.y, t = threadIdx.x;
    __shared__ float ms[F_];
    __shared__ float h1[H1_];
    __shared__ float h2[H2_];
    __shared__ float red[4];

    const float* mp = g_mean + ((size_t)b * MAXE + e) * F_;
    ms[t]       = mp[t];
    ms[t + 128] = mp[t + 128];
    __syncthreads();

    float s = m1b[t];
    for (int k = 0; k < F_; k++) s += ms[k] * m1w[k * H1_ + t];
    h1[t] = fmaxf(s, 0.f);
    __syncthreads();

    if (t < H2_) {
        float s2 = m2b[t];
        for (int k = 0; k < H1_; k++) s2 += h1[k] * m2w[k * H2_ + t];
        h2[t] = fmaxf(s2, 0.f);
    }
    __syncthreads();

    float p = (t < H2_) ? h2[t] * m3w[t] : 0.f;
#pragma unroll
    for (int off = 16; off; off >>= 1)
        p += __shfl_xor_sync(0xffffffffu, p, off);
    if ((t & 31) == 0) red[t >> 5] = p;
    __syncthreads();
    if (t == 0)
        g_ctx[b * MAXE + e] = red[0] + red[1] + red[2] + red[3] + m3b[0];
}

__global__ __launch_bounds__(256)
void aw_kernel(const float* __restrict__ x, const int* __restrict__ Hm,
               const float* __restrict__ cw, const float* __restrict__ cb,
               const float* __restrict__ hb, const float* __restrict__ alpha,
               float* __restrict__ out)
{
    const int n = blockIdx.x, b = blockIdx.y, t = threadIdx.x;
    __shared__ float red[8];
    __shared__ float compat_s;

    float p = x[((size_t)b * N_ + n) * F_ + t] * cw[t];
#pragma unroll
    for (int off = 16; off; off >>= 1)
        p += __shfl_xor_sync(0xffffffffu, p, off);
    if ((t & 31) == 0) red[t >> 5] = p;
    __syncthreads();
    if (t == 0) {
        float s = 0.f;
#pragma unroll
        for (int i = 0; i < 8; i++) s += red[i];
        compat_s = s + cb[0] + hb[0];
    }
    __syncthreads();

    float val = 0.f;
    if (t < MAXE) {
        if (Hm[(size_t)n * E_ + t] && g_deg[t] > 1.0f) {
            float z = compat_s + alpha[0] * g_ctx[b * MAXE + t];
            val = 1.f / (1.f + __expf(-z));
        }
    }
    out[((size_t)b * N_ + n) * OUTC + t] = val;
}

// ---------------------------------------------------------------------------
// Launch
// ---------------------------------------------------------------------------
extern "C" void kernel_launch(void* const* d_in, const int* in_sizes, int n_in,
                              void* d_out, int out_size)
{
    const float* x      = (const float*)d_in[0];
    const int*   Hm     = (const int*)  d_in[1];
    const float* weight = (const float*)d_in[2];
    const float* bias   = (const float*)d_in[3];
    const float* Wn_w   = (const float*)d_in[4];
    const float* Wn_b   = (const float*)d_in[5];
    const float* m1_w   = (const float*)d_in[6];
    const float* m1_b   = (const float*)d_in[7];
    const float* m2_w   = (const float*)d_in[8];
    const float* m2_b   = (const float*)d_in[9];
    const float* m3_w   = (const float*)d_in[10];
    const float* m3_b   = (const float*)d_in[11];
    const float* c_w    = (const float*)d_in[12];
    const float* c_b    = (const float*)d_in[13];
    const float* hedgeb = (const float*)d_in[14];
    const float* alpha  = (const float*)d_in[15];
    float* out = (float*)d_out;

    float* v;
    __nv_bfloat16 *Sb, *xh, *xl, *xph, *xpl, *vth, *vtl, *Ph, *Pl;
    __nv_bfloat16 *wth, *wtl, *wnth, *wntl;
    cudaGetSymbolAddress((void**)&v,   g_v);
    cudaGetSymbolAddress((void**)&Sb,  g_Sb);
    cudaGetSymbolAddress((void**)&xh,  g_xh);
    cudaGetSymbolAddress((void**)&xl,  g_xl);
    cudaGetSymbolAddress((void**)&xph, g_xph);
    cudaGetSymbolAddress((void**)&xpl, g_xpl);
    cudaGetSymbolAddress((void**)&vth, g_vth);
    cudaGetSymbolAddress((void**)&vtl, g_vtl);
    cudaGetSymbolAddress((void**)&Ph,  g_Ph);
    cudaGetSymbolAddress((void**)&Pl,  g_Pl);
    cudaGetSymbolAddress((void**)&wth, g_wth);
    cudaGetSymbolAddress((void**)&wtl, g_wtl);
    cudaGetSymbolAddress((void**)&wnth, g_wnth);
    cudaGetSymbolAddress((void**)&wntl, g_wntl);

    cudaFuncSetAttribute(gemm_sym,
                         cudaFuncAttributeMaxDynamicSharedMemorySize, GEMM_SMEM);
    cudaFuncSetAttribute(gemm_wide<0>,
                         cudaFuncAttributeMaxDynamicSharedMemorySize, WGEMM_SMEM);
    cudaFuncSetAttribute(gemm_wide<2>,
                         cudaFuncAttributeMaxDynamicSharedMemorySize, WGEMM_SMEM);

    const int nx = B_ * N_ * F_;   // 4M elements

    // hyperedge branch (independent)
    edge_mean_kernel<<<dim3(MAXE, B_), 256>>>(x, Hm);
    ctx_kernel<<<dim3(MAXE, B_), 128>>>(m1_w, m1_b, m2_w, m2_b, m3_w, m3_b);
    aw_kernel<<<dim3(N_, B_), 256>>>(x, Hm, c_w, c_b, hedgeb, alpha, out);

    // input conversions
    conv_split<<<nx / 4 / 256, 256>>>(x, xh, xl, nx);
    transpose_split<<<dim3(8, 8, 1), dim3(32, 8)>>>(weight, wth, wtl, F_, F_, 0, 0);
    transpose_split<<<dim3(8, 8, 1), dim3(32, 8)>>>(Wn_w, wnth, wntl, F_, F_, 0, 0);

    // projections: xp = x@Wn_w + Wn_b (split emitted) ; v = x@weight (fp32)
    gemm_wide<2><<<dim3(1, (B_ * N_) / 128, 1), 256, WGEMM_SMEM>>>(
        xh, xl, wnth, wntl, xph, xpl, Wn_b, F_, F_, 0, 0, 0, 1.0f);
    gemm_wide<0><<<dim3(1, (B_ * N_) / 128, 1), 256, WGEMM_SMEM>>>(
        xh, xl, wth, wtl, v, nullptr, nullptr, F_, F_, 0, 0, 0, 1.0f);

    // v transposed per batch -> bf16 hi/lo
    transpose_split<<<dim3(F_ / 32, N_ / 32, B_), dim3(32, 8)>>>(
        v, vth, vtl, N_, F_, (long long)N_ * F_, (long long)F_ * N_);

    // S = xp @ xp^T / 16 -> bf16, symmetric: 528 upper-triangle tiles + mirror
    gemm_sym<<<dim3(528, 1, B_), 256, GEMM_SMEM>>>(
        xph, xpl, Sb, F_, N_,
        (long long)N_ * F_, (long long)N_ * N_, 0.0625f);

    // P = softmax(S) -> bf16 hi/lo
    softmax_split_b<<<dim3(N_, 1, B_), 256>>>(Sb, Ph, Pl);

    // y = P @ V + bias -> out[..., E:E+F]
    gemm_wide<0><<<dim3(1, N_ / 128, B_), 256, WGEMM_SMEM>>>(
        Ph, Pl, vth, vtl, out + E_, nullptr, bias, N_, OUTC,
        (long long)N_ * N_, (long long)F_ * N_, (long long)N_ * OUTC, 1.0f);
}

// round 14
// speedup vs baseline: 1.0351x; 1.0328x over previous
#include <cuda_runtime.h>
#include <cuda_bf16.h>
#include <cstdint>
#include <cstddef>

// Problem constants
#define B_   4
#define N_   4096
#define E_   256
#define F_   256
#define MAXE 50
#define H1_  128
#define H2_  64
#define OUTC 512

// ---------------------------------------------------------------------------
// Static device scratch
// ---------------------------------------------------------------------------
__device__ __nv_bfloat16 g_Sb[67108864];             // scores bf16 (128 MB)
__device__ __nv_bfloat16 g_xh [B_ * N_ * F_];        // x hi
__device__ __nv_bfloat16 g_xl [B_ * N_ * F_];        // x lo
__device__ __nv_bfloat16 g_xph[B_ * N_ * F_];        // xp hi
__device__ __nv_bfloat16 g_xpl[B_ * N_ * F_];
__device__ __nv_bfloat16 g_vth[B_ * F_ * N_];        // v^T hi  [b][256][4096]
__device__ __nv_bfloat16 g_vtl[B_ * F_ * N_];
__device__ __nv_bfloat16 g_Ph [67108864];            // softmax(S) hi (128 MB)
__device__ __nv_bfloat16 g_Pl [67108864];            // softmax(S) lo (128 MB)
__device__ __nv_bfloat16 g_wth [F_ * F_], g_wtl [F_ * F_];   // weight^T hi/lo
__device__ __nv_bfloat16 g_wnth[F_ * F_], g_wntl[F_ * F_];   // Wn_w^T hi/lo
__device__ float g_mean[B_ * MAXE * F_];
__device__ float g_ctx [B_ * MAXE];
__device__ float g_deg [MAXE];

// ---------------------------------------------------------------------------
// PTX helpers (base sm_100-safe: mma.sync / ldmatrix / cp.async)
// ---------------------------------------------------------------------------
__device__ __forceinline__ uint32_t smem_u32(const void* p) {
    uint32_t a;
    asm("{ .reg .u64 t; cvta.to.shared.u64 t, %1; cvt.u32.u64 %0, t; }"
        : "=r"(a) : "l"(p));
    return a;
}
__device__ __forceinline__ void cp_async16(uint32_t s, const void* g) {
    asm volatile("cp.async.cg.shared.global [%0], [%1], 16;\n"
        :: "r"(s), "l"((unsigned long long)__cvta_generic_to_global(g)) : "memory");
}
__device__ __forceinline__ void cp_commit() {
    asm volatile("cp.async.commit_group;\n" ::: "memory");
}
__device__ __forceinline__ void cp_wait0() {
    asm volatile("cp.async.wait_group 0;\n" ::: "memory");
}
__device__ __forceinline__ void cp_wait1() {
    asm volatile("cp.async.wait_group 1;\n" ::: "memory");
}
__device__ __forceinline__ void ldmatrix_x4(uint32_t* r, uint32_t addr) {
    asm volatile("ldmatrix.sync.aligned.m8n8.x4.shared.b16 {%0,%1,%2,%3}, [%4];\n"
        : "=r"(r[0]), "=r"(r[1]), "=r"(r[2]), "=r"(r[3]) : "r"(addr));
}
__device__ __forceinline__ void mma_bf16(float* d, const uint32_t* a,
                                         uint32_t b0, uint32_t b1) {
    asm volatile(
        "mma.sync.aligned.m16n8k16.row.col.f32.bf16.bf16.f32 "
        "{%0,%1,%2,%3}, {%4,%5,%6,%7}, {%8,%9}, {%0,%1,%2,%3};\n"
        : "+f"(d[0]), "+f"(d[1]), "+f"(d[2]), "+f"(d[3])
        : "r"(a[0]), "r"(a[1]), "r"(a[2]), "r"(a[3]), "r"(b0), "r"(b1));
}

// ---------------------------------------------------------------------------
// bf16 split GEMM via mma.sync (Round-10 proven config):
// D[m][n] = scale*sum_k A[m,k]*B[n,k] (+bias)
// NPASS=3: AhBh + AlBh + AhBl.  NPASS=2: AhBh + AlBh.
// OMODE=0: fp32 out. OMODE=1: bf16 out. OMODE=2: bf16 hi/lo out.
// SYM=1: A==B; grid.x enumerates 528 upper-triangle 128x128 tile pairs;
//        each CTA also writes the transposed mirror (requires OMODE==1).
// CTA tile 128x128, K-chunk 64, 256 threads (8 warps 2m x 4n, warp 64x32).
// Smem: 3 stages x 32KB = 96KB. Depth-2 cp.async prefetch.
// ---------------------------------------------------------------------------
#define GEMM_SMEM (3 * 32768)

template <int NPASS, int OMODE, int SYM>
__global__ __launch_bounds__(256)
void gemm_bf16s(const __nv_bfloat16* __restrict__ Ah, const __nv_bfloat16* __restrict__ Al,
                const __nv_bfloat16* __restrict__ Bh, const __nv_bfloat16* __restrict__ Bl,
                void* __restrict__ C0p, void* __restrict__ C1p,
                const float* __restrict__ bias, int K, int ldc,
                long long sA, long long sB, long long sC, float scale)
{
    extern __shared__ __align__(16) char smem[];
    const uint32_t sbase = smem_u32(smem);
    const int tid = threadIdx.x;
    const int lane = tid & 31;
    const int wid = tid >> 5;
    const int wm = wid & 1;
    const int wn = wid >> 1;

    size_t Ms, Ns;
    int ibl = 0, jbl = 0;
    if (SYM) {
        const int NT = 32;
        int t = blockIdx.x;
        int i = (int)((2.f * NT + 1.f -
                       sqrtf((2.f * NT + 1.f) * (2.f * NT + 1.f) - 8.f * t)) * 0.5f);
        while ((i + 1) * NT - ((i + 1) * i) / 2 <= t) i++;
        while (i * NT - (i * (i - 1)) / 2 > t) i--;
        int j = i + (t - (i * NT - (i * (i - 1)) / 2));
        ibl = i; jbl = j;
        Ms = (size_t)i * 128;
        Ns = (size_t)j * 128;
    } else {
        Ms = (size_t)blockIdx.y * 128;
        Ns = (size_t)blockIdx.x * 128;
    }
    const int z = blockIdx.z;
    const __nv_bfloat16* pAh = Ah + (size_t)z * sA + Ms * K;
    const __nv_bfloat16* pAl = Al + (size_t)z * sA + Ms * K;
    const __nv_bfloat16* pBh = Bh + (size_t)z * sB + Ns * K;
    const __nv_bfloat16* pBl = Bl + (size_t)z * sB + Ns * K;

    const int KC = K >> 6;
    const int T = NPASS * KC;

    float acc[4][4][4];
#pragma unroll
    for (int i = 0; i < 4; i++)
#pragma unroll
        for (int j = 0; j < 4; j++)
#pragma unroll
            for (int k = 0; k < 4; k++) acc[i][j][k] = 0.f;

    auto load_chunk = [&](int t) {
        const int pass = t / KC;
        const int kk = (t - pass * KC) << 6;
        const __nv_bfloat16* pA = (pass == 1) ? pAl : pAh;
        const __nv_bfloat16* pB = (pass == 2) ? pBl : pBh;
        const uint32_t st = sbase + (t % 3) * 32768;
#pragma unroll
        for (int i = 0; i < 4; i++) {
            int idx = i * 256 + tid;
            int row = idx >> 3, c = idx & 7;
            uint32_t sa = st + row * 128 + ((c ^ (row & 7)) << 4);
            cp_async16(sa, pA + (size_t)row * K + kk + c * 8);
        }
#pragma unroll
        for (int i = 0; i < 4; i++) {
            int idx = i * 256 + tid;
            int row = idx >> 3, c = idx & 7;
            uint32_t sa = st + 16384 + row * 128 + ((c ^ (row & 7)) << 4);
            cp_async16(sa, pB + (size_t)row * K + kk + c * 8);
        }
        cp_commit();
    };

    load_chunk(0);
    load_chunk(1);

#pragma unroll 1
    for (int t = 0; t < T; t++) {
        if (t + 1 < T) cp_wait1(); else cp_wait0();
        __syncthreads();
        if (t + 2 < T) load_chunk(t + 2);

        const uint32_t Ab = sbase + (t % 3) * 32768;
        const uint32_t Bb = Ab + 16384;
#pragma unroll
        for (int ks = 0; ks < 4; ks++) {
            uint32_t afr[4][4];
#pragma unroll
            for (int mt = 0; mt < 4; mt++) {
                int arow = wm * 64 + mt * 16 + (lane & 15);
                int c = ks * 2 + (lane >> 4);
                ldmatrix_x4(afr[mt], Ab + arow * 128 + ((c ^ (arow & 7)) << 4));
            }
            uint32_t bfr[2][4];
#pragma unroll
            for (int np = 0; np < 2; np++) {
                int nrow = wn * 32 + np * 16 + (lane & 7) + ((lane >> 4) << 3);
                int c = ks * 2 + ((lane >> 3) & 1);
                ldmatrix_x4(bfr[np], Bb + nrow * 128 + ((c ^ (nrow & 7)) << 4));
            }
#pragma unroll
            for (int mt = 0; mt < 4; mt++)
#pragma unroll
                for (int nt = 0; nt < 4; nt++)
                    mma_bf16(acc[mt][nt], afr[mt],
                             bfr[nt >> 1][(nt & 1) * 2],
                             bfr[nt >> 1][(nt & 1) * 2 + 1]);
        }
    }

    __nv_bfloat16* stg = (__nv_bfloat16*)smem;     // [128][136]
    if (SYM) __syncthreads();

    const int tg = lane >> 2, tq = lane & 3;
#pragma unroll
    for (int mt = 0; mt < 4; mt++) {
#pragma unroll
        for (int nt = 0; nt < 4; nt++) {
            int r0 = wm * 64 + mt * 16 + tg;
            int cc = wn * 32 + nt * 8 + tq * 2;
            float b0 = 0.f, b1 = 0.f;
            if (bias) { b0 = bias[Ns + cc]; b1 = bias[Ns + cc + 1]; }
            float v00 = acc[mt][nt][0] * scale + b0;
            float v01 = acc[mt][nt][1] * scale + b1;
            float v10 = acc[mt][nt][2] * scale + b0;
            float v11 = acc[mt][nt][3] * scale + b1;
            if (OMODE == 0) {
                float* pC = (float*)C0p + (size_t)z * sC + Ms * ldc + Ns;
                float2 w0 = { v00, v01 }, w1 = { v10, v11 };
                *(float2*)(pC + (size_t)r0 * ldc + cc)       = w0;
                *(float2*)(pC + (size_t)(r0 + 8) * ldc + cc) = w1;
            } else if (OMODE == 1) {
                __nv_bfloat16* pC = (__nv_bfloat16*)C0p + (size_t)z * sC + Ms * ldc + Ns;
                __nv_bfloat16 h00 = __float2bfloat16(v00), h01 = __float2bfloat16(v01);
                __nv_bfloat16 h10 = __float2bfloat16(v10), h11 = __float2bfloat16(v11);
                *(__nv_bfloat162*)(pC + (size_t)r0 * ldc + cc) = __nv_bfloat162(h00, h01);
                *(__nv_bfloat162*)(pC + (size_t)(r0 + 8) * ldc + cc) = __nv_bfloat162(h10, h11);
                if (SYM) {
                    stg[r0 * 136 + cc]           = h00;
                    stg[r0 * 136 + cc + 1]       = h01;
                    stg[(r0 + 8) * 136 + cc]     = h10;
                    stg[(r0 + 8) * 136 + cc + 1] = h11;
                }
            } else {
                __nv_bfloat16* pH = (__nv_bfloat16*)C0p + (size_t)z * sC + Ms * ldc + Ns;
                __nv_bfloat16* pL = (__nv_bfloat16*)C1p + (size_t)z * sC + Ms * ldc + Ns;
                __nv_bfloat16 h00 = __float2bfloat16(v00), h01 = __float2bfloat16(v01);
                __nv_bfloat16 h10 = __float2bfloat16(v10), h11 = __float2bfloat16(v11);
                *(__nv_bfloat162*)(pH + (size_t)r0 * ldc + cc) = __nv_bfloat162(h00, h01);
                *(__nv_bfloat162*)(pH + (size_t)(r0 + 8) * ldc + cc) = __nv_bfloat162(h10, h11);
                *(__nv_bfloat162*)(pL + (size_t)r0 * ldc + cc) =
                    __nv_bfloat162(__float2bfloat16(v00 - __bfloat162float(h00)),
                                   __float2bfloat16(v01 - __bfloat162float(h01)));
                *(__nv_bfloat162*)(pL + (size_t)(r0 + 8) * ldc + cc) =
                    __nv_bfloat162(__float2bfloat16(v10 - __bfloat162float(h10)),
                                   __float2bfloat16(v11 - __bfloat162float(h11)));
            }
        }
    }

    if (SYM && ibl != jbl) {
        __syncthreads();
        __nv_bfloat16* pT = (__nv_bfloat16*)C0p + (size_t)z * sC + Ns * ldc + Ms;
        const int orow = tid >> 1;
        const int half = tid & 1;
#pragma unroll
        for (int q = 0; q < 8; q++) {
            int c0 = half * 64 + q * 8;
            __nv_bfloat16 tmp[8];
#pragma unroll
            for (int e = 0; e < 8; e++)
                tmp[e] = stg[(c0 + e) * 136 + orow];
            *(uint4*)(pT + (size_t)orow * ldc + c0) = *(uint4*)tmp;
        }
    }
}

// ---------------------------------------------------------------------------
// fp32 -> (bf16 hi, bf16 lo) split, 4 elements/thread
// ---------------------------------------------------------------------------
__global__ __launch_bounds__(256)
void conv_split(const float* __restrict__ in, __nv_bfloat16* __restrict__ hi,
                __nv_bfloat16* __restrict__ lo, int n)
{
    int i = (blockIdx.x * 256 + threadIdx.x) * 4;
    if (i >= n) return;
    float4 v = *(const float4*)(in + i);
    __nv_bfloat16 h0 = __float2bfloat16(v.x), h1 = __float2bfloat16(v.y);
    __nv_bfloat16 h2 = __float2bfloat16(v.z), h3 = __float2bfloat16(v.w);
    __nv_bfloat162 ph0(h0, h1), ph1(h2, h3);
    __nv_bfloat162 pl0(__float2bfloat16(v.x - __bfloat162float(h0)),
                       __float2bfloat16(v.y - __bfloat162float(h1)));
    __nv_bfloat162 pl1(__float2bfloat16(v.z - __bfloat162float(h2)),
                       __float2bfloat16(v.w - __bfloat162float(h3)));
    *(__nv_bfloat162*)(hi + i)     = ph0;
    *(__nv_bfloat162*)(hi + i + 2) = ph1;
    *(__nv_bfloat162*)(lo + i)     = pl0;
    *(__nv_bfloat162*)(lo + i + 2) = pl1;
}

// ---------------------------------------------------------------------------
// transpose + split (weights only): in [R][C] fp32 -> out [C][R] bf16 hi/lo
// ---------------------------------------------------------------------------
__global__ __launch_bounds__(256)
void transpose_split(const float* __restrict__ in, __nv_bfloat16* __restrict__ oh,
                     __nv_bfloat16* __restrict__ ol, int R, int C,
                     long long sIn, long long sOut)
{
    __shared__ float tile[32][33];
    const int c0 = blockIdx.x * 32, r0 = blockIdx.y * 32, z = blockIdx.z;
    in += (size_t)z * sIn; oh += (size_t)z * sOut; ol += (size_t)z * sOut;
    const int tx = threadIdx.x, ty = threadIdx.y;
#pragma unroll
    for (int j = 0; j < 4; j++)
        tile[ty + 8 * j][tx] = in[(size_t)(r0 + ty + 8 * j) * C + c0 + tx];
    __syncthreads();
#pragma unroll
    for (int j = 0; j < 4; j++) {
        float v = tile[tx][ty + 8 * j];
        __nv_bfloat16 h = __float2bfloat16(v);
        size_t o = (size_t)(c0 + ty + 8 * j) * R + r0 + tx;
        oh[o] = h;
        ol[o] = __float2bfloat16(v - __bfloat162float(h));
    }
}

// ---------------------------------------------------------------------------
// Row softmax on bf16 S -> bf16 hi/lo P. grid (4096, 1, B), 256 threads.
// ---------------------------------------------------------------------------
__global__ __launch_bounds__(256)
void softmax_split_b(const __nv_bfloat16* __restrict__ S,
                     __nv_bfloat16* __restrict__ Ph, __nv_bfloat16* __restrict__ Pl)
{
    const size_t row = (size_t)blockIdx.z * N_ + blockIdx.x;
    const uint4* r4 = (const uint4*)(S + row * N_);
    uint4* ph4 = (uint4*)(Ph + row * N_);
    uint4* pl4 = (uint4*)(Pl + row * N_);
    const int tid = threadIdx.x, lane = tid & 31, wid = tid >> 5;
    __shared__ float red[8];
    __shared__ float bval;

    uint4 u[2];
    u[0] = r4[tid];
    u[1] = r4[tid + 256];
    float v[16];
#pragma unroll
    for (int q = 0; q < 2; q++) {
        const uint32_t* w = (const uint32_t*)&u[q];
#pragma unroll
        for (int j = 0; j < 4; j++) {
            float2 f = __bfloat1622float2(*(const __nv_bfloat162*)&w[j]);
            v[q * 8 + j * 2]     = f.x;
            v[q * 8 + j * 2 + 1] = f.y;
        }
    }

    float mx = v[0];
#pragma unroll
    for (int j = 1; j < 16; j++) mx = fmaxf(mx, v[j]);
#pragma unroll
    for (int off = 16; off; off >>= 1)
        mx = fmaxf(mx, __shfl_xor_sync(0xffffffffu, mx, off));
    if (lane == 0) red[wid] = mx;
    __syncthreads();
    if (tid == 0) {
        float m = red[0];
#pragma unroll
        for (int i = 1; i < 8; i++) m = fmaxf(m, red[i]);
        bval = m;
    }
    __syncthreads();
    mx = bval;

    float s = 0.f;
#pragma unroll
    for (int j = 0; j < 16; j++) { v[j] = __expf(v[j] - mx); s += v[j]; }
#pragma unroll
    for (int off = 16; off; off >>= 1)
        s += __shfl_xor_sync(0xffffffffu, s, off);
    if (lane == 0) red[wid] = s;
    __syncthreads();
    if (tid == 0) {
        float t = 0.f;
#pragma unroll
        for (int i = 0; i < 8; i++) t += red[i];
        bval = 1.f / t;
    }
    __syncthreads();
    const float inv = bval;

    uint4 oh[2], ol[2];
#pragma unroll
    for (int q = 0; q < 2; q++) {
        uint32_t* wh = (uint32_t*)&oh[q];
        uint32_t* wl = (uint32_t*)&ol[q];
#pragma unroll
        for (int j = 0; j < 4; j++) {
            float a = v[q * 8 + j * 2] * inv;
            float b = v[q * 8 + j * 2 + 1] * inv;
            __nv_bfloat16 ha = __float2bfloat16(a), hb = __float2bfloat16(b);
            __nv_bfloat162 hp(ha, hb);
            __nv_bfloat162 lp(__float2bfloat16(a - __bfloat162float(ha)),
                              __float2bfloat16(b - __bfloat162float(hb)));
            wh[j] = *(uint32_t*)&hp;
            wl[j] = *(uint32_t*)&lp;
        }
    }
    ph4[tid]       = oh[0];
    ph4[tid + 256] = oh[1];
    pl4[tid]       = ol[0];
    pl4[tid + 256] = ol[1];
}

// ---------------------------------------------------------------------------
// Hyperedge branch
// ---------------------------------------------------------------------------
__global__ __launch_bounds__(256)
void edge_mean_kernel(const float* __restrict__ x, const int* __restrict__ Hm)
{
    const int e = blockIdx.x, b = blockIdx.y, f = threadIdx.x;
    const float* xb = x + (size_t)b * N_ * F_;
    float sum = 0.f;
    int cnt = 0;
    for (int n = 0; n < N_; n++) {
        if (Hm[(size_t)n * E_ + e]) {
            sum += xb[(size_t)n * F_ + f];
            cnt++;
        }
    }
    const float deg = (float)cnt;
    g_mean[((size_t)b * MAXE + e) * F_ + f] = sum / fmaxf(deg, 1.0f);
    if (f == 0 && b == 0) g_deg[e] = deg;
}

__global__ __launch_bounds__(128)
void ctx_kernel(const float* __restrict__ m1w, const float* __restrict__ m1b,
                const float* __restrict__ m2w, const float* __restrict__ m2b,
                const float* __restrict__ m3w, const float* __restrict__ m3b)
{
    const int e = blockIdx.x, b = blockIdx.y, t = threadIdx.x;
    __shared__ float ms[F_];
    __shared__ float h1[H1_];
    __shared__ float h2[H2_];
    __shared__ float red[4];

    const float* mp = g_mean + ((size_t)b * MAXE + e) * F_;
    ms[t]       = mp[t];
    ms[t + 128] = mp[t + 128];
    __syncthreads();

    float s = m1b[t];
    for (int k = 0; k < F_; k++) s += ms[k] * m1w[k * H1_ + t];
    h1[t] = fmaxf(s, 0.f);
    __syncthreads();

    if (t < H2_) {
        float s2 = m2b[t];
        for (int k = 0; k < H1_; k++) s2 += h1[k] * m2w[k * H2_ + t];
        h2[t] = fmaxf(s2, 0.f);
    }
    __syncthreads();

    float p = (t < H2_) ? h2[t] * m3w[t] : 0.f;
#pragma unroll
    for (int off = 16; off; off >>= 1)
        p += __shfl_xor_sync(0xffffffffu, p, off);
    if ((t & 31) == 0) red[t >> 5] = p;
    __syncthreads();
    if (t == 0)
        g_ctx[b * MAXE + e] = red[0] + red[1] + red[2] + red[3] + m3b[0];
}

__global__ __launch_bounds__(256)
void aw_kernel(const float* __restrict__ x, const int* __restrict__ Hm,
               const float* __restrict__ cw, const float* __restrict__ cb,
               const float* __restrict__ hb, const float* __restrict__ alpha,
               float* __restrict__ out)
{
    const int n = blockIdx.x, b = blockIdx.y, t = threadIdx.x;
    __shared__ float red[8];
    __shared__ float compat_s;

    float p = x[((size_t)b * N_ + n) * F_ + t] * cw[t];
#pragma unroll
    for (int off = 16; off; off >>= 1)
        p += __shfl_xor_sync(0xffffffffu, p, off);
    if ((t & 31) == 0) red[t >> 5] = p;
    __syncthreads();
    if (t == 0) {
        float s = 0.f;
#pragma unroll
        for (int i = 0; i < 8; i++) s += red[i];
        compat_s = s + cb[0] + hb[0];
    }
    __syncthreads();

    float val = 0.f;
    if (t < MAXE) {
        if (Hm[(size_t)n * E_ + t] && g_deg[t] > 1.0f) {
            float z = compat_s + alpha[0] * g_ctx[b * MAXE + t];
            val = 1.f / (1.f + __expf(-z));
        }
    }
    out[((size_t)b * N_ + n) * OUTC + t] = val;
}

// ---------------------------------------------------------------------------
// Launch
// ---------------------------------------------------------------------------
extern "C" void kernel_launch(void* const* d_in, const int* in_sizes, int n_in,
                              void* d_out, int out_size)
{
    const float* x      = (const float*)d_in[0];
    const int*   Hm     = (const int*)  d_in[1];
    const float* weight = (const float*)d_in[2];
    const float* bias   = (const float*)d_in[3];
    const float* Wn_w   = (const float*)d_in[4];
    const float* Wn_b   = (const float*)d_in[5];
    const float* m1_w   = (const float*)d_in[6];
    const float* m1_b   = (const float*)d_in[7];
    const float* m2_w   = (const float*)d_in[8];
    const float* m2_b   = (const float*)d_in[9];
    const float* m3_w   = (const float*)d_in[10];
    const float* m3_b   = (const float*)d_in[11];
    const float* c_w    = (const float*)d_in[12];
    const float* c_b    = (const float*)d_in[13];
    const float* hedgeb = (const float*)d_in[14];
    const float* alpha  = (const float*)d_in[15];
    float* out = (float*)d_out;

    __nv_bfloat16 *Sb, *xh, *xl, *xph, *xpl, *vth, *vtl, *Ph, *Pl;
    __nv_bfloat16 *wth, *wtl, *wnth, *wntl;
    cudaGetSymbolAddress((void**)&Sb,  g_Sb);
    cudaGetSymbolAddress((void**)&xh,  g_xh);
    cudaGetSymbolAddress((void**)&xl,  g_xl);
    cudaGetSymbolAddress((void**)&xph, g_xph);
    cudaGetSymbolAddress((void**)&xpl, g_xpl);
    cudaGetSymbolAddress((void**)&vth, g_vth);
    cudaGetSymbolAddress((void**)&vtl, g_vtl);
    cudaGetSymbolAddress((void**)&Ph,  g_Ph);
    cudaGetSymbolAddress((void**)&Pl,  g_Pl);
    cudaGetSymbolAddress((void**)&wth, g_wth);
    cudaGetSymbolAddress((void**)&wtl, g_wtl);
    cudaGetSymbolAddress((void**)&wnth, g_wnth);
    cudaGetSymbolAddress((void**)&wntl, g_wntl);

    cudaFuncSetAttribute(gemm_bf16s<3, 0, 0>,
                         cudaFuncAttributeMaxDynamicSharedMemorySize, GEMM_SMEM);
    cudaFuncSetAttribute(gemm_bf16s<3, 2, 0>,
                         cudaFuncAttributeMaxDynamicSharedMemorySize, GEMM_SMEM);
    cudaFuncSetAttribute(gemm_bf16s<2, 1, 1>,
                         cudaFuncAttributeMaxDynamicSharedMemorySize, GEMM_SMEM);

    const int nx = B_ * N_ * F_;   // 4M elements

    // hyperedge branch (independent)
    edge_mean_kernel<<<dim3(MAXE, B_), 256>>>(x, Hm);
    ctx_kernel<<<dim3(MAXE, B_), 128>>>(m1_w, m1_b, m2_w, m2_b, m3_w, m3_b);
    aw_kernel<<<dim3(N_, B_), 256>>>(x, Hm, c_w, c_b, hedgeb, alpha, out);

    // input conversions
    conv_split<<<nx / 4 / 256, 256>>>(x, xh, xl, nx);
    transpose_split<<<dim3(8, 8, 1), dim3(32, 8)>>>(weight, wth, wtl, F_, F_, 0, 0);
    transpose_split<<<dim3(8, 8, 1), dim3(32, 8)>>>(Wn_w, wnth, wntl, F_, F_, 0, 0);

    // xp = x@Wn_w + Wn_b (bf16 hi/lo emitted directly)
    gemm_bf16s<3, 2, 0><<<dim3(F_ / 128, (B_ * N_) / 128, 1), 256, GEMM_SMEM>>>(
        xh, xl, wnth, wntl, xph, xpl, Wn_b, F_, F_, 0, 0, 0, 1.0f);

    // v^T[f][n] = sum_k weight^T[f][k] * x[n][k]  (bf16 hi/lo emitted directly)
    // A = wth/wtl [F][F], B = xh/xl per batch, C = vth/vtl [F][N] ldc=N
    gemm_bf16s<3, 2, 0><<<dim3(N_ / 128, F_ / 128, B_), 256, GEMM_SMEM>>>(
        wth, wtl, xh, xl, vth, vtl, nullptr, F_, N_,
        0, (long long)N_ * F_, (long long)F_ * N_, 1.0f);

    // S = xp @ xp^T / 16 -> bf16, symmetric: 528 upper-triangle tiles + mirror
    gemm_bf16s<2, 1, 1><<<dim3(528, 1, B_), 256, GEMM_SMEM>>>(
        xph, xpl, xph, xpl, Sb, nullptr, nullptr, F_, N_,
        (long long)N_ * F_, (long long)N_ * F_, (long long)N_ * N_, 0.0625f);

    // P = softmax(S) -> bf16 hi/lo
    softmax_split_b<<<dim3(N_, 1, B_), 256>>>(Sb, Ph, Pl);

    // y = P @ V + bias -> out[..., E:E+F]
    gemm_bf16s<3, 0, 0><<<dim3(F_ / 128, N_ / 128, B_), 256, GEMM_SMEM>>>(
        Ph, Pl, vth, vtl, out + E_, nullptr, bias, N_, OUTC,
        (long long)N_ * N_, (long long)F_ * N_, (long long)N_ * OUTC, 1.0f);
}

// round 16
// speedup vs baseline: 1.1875x; 1.1472x over previous
#include <cuda_runtime.h>
#include <cuda_bf16.h>
#include <cstdint>
#include <cstddef>

// Problem constants
#define B_   4
#define N_   4096
#define E_   256
#define F_   256
#define MAXE 50
#define H1_  128
#define H2_  64
#define OUTC 512

// ---------------------------------------------------------------------------
// Static device scratch
// ---------------------------------------------------------------------------
__device__ __nv_bfloat16 g_Sb[67108864];             // scores bf16 (128 MB)
__device__ __nv_bfloat16 g_xh [B_ * N_ * F_];        // x hi
__device__ __nv_bfloat16 g_xl [B_ * N_ * F_];        // x lo
__device__ __nv_bfloat16 g_xph[B_ * N_ * F_];        // xp hi
__device__ __nv_bfloat16 g_xpl[B_ * N_ * F_];
__device__ __nv_bfloat16 g_vth[B_ * F_ * N_];        // v^T hi  [b][256][4096]
__device__ __nv_bfloat16 g_Ph [67108864];            // softmax(S) hi (128 MB)
__device__ __nv_bfloat16 g_Pl [67108864];            // softmax(S) lo (128 MB)
__device__ __nv_bfloat16 g_wth [F_ * F_], g_wtl [F_ * F_];   // weight^T hi/lo
__device__ __nv_bfloat16 g_wnth[F_ * F_], g_wntl[F_ * F_];   // Wn_w^T hi/lo
__device__ float g_mean[B_ * MAXE * F_];
__device__ float g_ctx [B_ * MAXE];
__device__ float g_deg [MAXE];

// ---------------------------------------------------------------------------
// PTX helpers (base sm_100-safe: mma.sync / ldmatrix / cp.async)
// ---------------------------------------------------------------------------
__device__ __forceinline__ uint32_t smem_u32(const void* p) {
    uint32_t a;
    asm("{ .reg .u64 t; cvta.to.shared.u64 t, %1; cvt.u32.u64 %0, t; }"
        : "=r"(a) : "l"(p));
    return a;
}
__device__ __forceinline__ void cp_async16(uint32_t s, const void* g) {
    asm volatile("cp.async.cg.shared.global [%0], [%1], 16;\n"
        :: "r"(s), "l"((unsigned long long)__cvta_generic_to_global(g)) : "memory");
}
__device__ __forceinline__ void cp_commit() {
    asm volatile("cp.async.commit_group;\n" ::: "memory");
}
__device__ __forceinline__ void cp_wait0() {
    asm volatile("cp.async.wait_group 0;\n" ::: "memory");
}
__device__ __forceinline__ void cp_wait1() {
    asm volatile("cp.async.wait_group 1;\n" ::: "memory");
}
__device__ __forceinline__ void ldmatrix_x4(uint32_t* r, uint32_t addr) {
    asm volatile("ldmatrix.sync.aligned.m8n8.x4.shared.b16 {%0,%1,%2,%3}, [%4];\n"
        : "=r"(r[0]), "=r"(r[1]), "=r"(r[2]), "=r"(r[3]) : "r"(addr));
}
__device__ __forceinline__ void mma_bf16(float* d, const uint32_t* a,
                                         uint32_t b0, uint32_t b1) {
    asm volatile(
        "mma.sync.aligned.m16n8k16.row.col.f32.bf16.bf16.f32 "
        "{%0,%1,%2,%3}, {%4,%5,%6,%7}, {%8,%9}, {%0,%1,%2,%3};\n"
        : "+f"(d[0]), "+f"(d[1]), "+f"(d[2]), "+f"(d[3])
        : "r"(a[0]), "r"(a[1]), "r"(a[2]), "r"(a[3]), "r"(b0), "r"(b1));
}

// ---------------------------------------------------------------------------
// bf16 split GEMM via mma.sync (Round-10 proven config):
// D[m][n] = scale*sum_k A[m,k]*B[n,k] (+bias)
// NPASS=3: AhBh + AlBh + AhBl.  NPASS=2: AhBh + AlBh.
// OMODE=0: fp32 out. OMODE=1: bf16 out. OMODE=2: bf16 hi/lo out.
// SYM=1: A==B (pass the same pointers for A and B); grid.x enumerates 528
//        upper-triangle 128x128 tile pairs; each CTA also writes the
//        transposed mirror (requires OMODE==1).
// CTA tile 128x128, K-chunk 64, 256 threads (8 warps 2m x 4n, warp 64x32).
// Smem: 3 stages x 32KB = 96KB. Depth-2 cp.async prefetch.
// ---------------------------------------------------------------------------
#define GEMM_SMEM (3 * 32768)

template <int NPASS, int OMODE, int SYM>
__global__ __launch_bounds__(256)
void gemm_bf16s(const __nv_bfloat16* __restrict__ Ah, const __nv_bfloat16* __restrict__ Al,
                const __nv_bfloat16* __restrict__ Bh, const __nv_bfloat16* __restrict__ Bl,
                void* __restrict__ C0p, void* __restrict__ C1p,
                const float* __restrict__ bias, int K, int ldc,
                long long sA, long long sB, long long sC, float scale)
{
    extern __shared__ __align__(16) char smem[];
    const uint32_t sbase = smem_u32(smem);
    const int tid = threadIdx.x;
    const int lane = tid & 31;
    const int wid = tid >> 5;
    const int wm = wid & 1;
    const int wn = wid >> 1;

    size_t Ms, Ns;
    int ibl = 0, jbl = 0;
    if (SYM) {
        const int NT = 32;
        int t = blockIdx.x;
        int i = (int)((2.f * NT + 1.f -
                       sqrtf((2.f * NT + 1.f) * (2.f * NT + 1.f) - 8.f * t)) * 0.5f);
        while ((i + 1) * NT - ((i + 1) * i) / 2 <= t) i++;
        while (i * NT - (i * (i - 1)) / 2 > t) i--;
        int j = i + (t - (i * NT - (i * (i - 1)) / 2));
        ibl = i; jbl = j;
        Ms = (size_t)i * 128;
        Ns = (size_t)j * 128;
    } else {
        Ms = (size_t)blockIdx.y * 128;
        Ns = (size_t)blockIdx.x * 128;
    }
    const int z = blockIdx.z;
    const __nv_bfloat16* pAh = Ah + (size_t)z * sA + Ms * K;
    const __nv_bfloat16* pAl = Al + (size_t)z * sA + Ms * K;
    const __nv_bfloat16* pBh = Bh + (size_t)z * sB + Ns * K;
    const __nv_bfloat16* pBl = Bl + (size_t)z * sB + Ns * K;

    const int KC = K >> 6;
    const int T = NPASS * KC;

    float acc[4][4][4];
#pragma unroll
    for (int i = 0; i < 4; i++)
#pragma unroll
        for (int j = 0; j < 4; j++)
#pragma unroll
            for (int k = 0; k < 4; k++) acc[i][j][k] = 0.f;

    auto load_chunk = [&](int t) {
        const int pass = t / KC;
        const int kk = (t - pass * KC) << 6;
        const __nv_bfloat16* pA = (pass == 1) ? pAl : pAh;
        const __nv_bfloat16* pB = (pass == 2) ? pBl : pBh;
        const uint32_t st = sbase + (t % 3) * 32768;
#pragma unroll
        for (int i = 0; i < 4; i++) {
            int idx = i * 256 + tid;
            int row = idx >> 3, c = idx & 7;
            uint32_t sa = st + row * 128 + ((c ^ (row & 7)) << 4);
            cp_async16(sa, pA + (size_t)row * K + kk + c * 8);
        }
#pragma unroll
        for (int i = 0; i < 4; i++) {
            int idx = i * 256 + tid;
            int row = idx >> 3, c = idx & 7;
            uint32_t sa = st + 16384 + row * 128 + ((c ^ (row & 7)) << 4);
            cp_async16(sa, pB + (size_t)row * K + kk + c * 8);
        }
        cp_commit();
    };

    load_chunk(0);
    load_chunk(1);

#pragma unroll 1
    for (int t = 0; t < T; t++) {
        if (t + 1 < T) cp_wait1(); else cp_wait0();
        __syncthreads();
        if (t + 2 < T) load_chunk(t + 2);

        const uint32_t Ab = sbase + (t % 3) * 32768;
        const uint32_t Bb = Ab + 16384;
#pragma unroll
        for (int ks = 0; ks < 4; ks++) {
            uint32_t afr[4][4];
#pragma unroll
            for (int mt = 0; mt < 4; mt++) {
                int arow = wm * 64 + mt * 16 + (lane & 15);
                int c = ks * 2 + (lane >> 4);
                ldmatrix_x4(afr[mt], Ab + arow * 128 + ((c ^ (arow & 7)) << 4));
            }
            uint32_t bfr[2][4];
#pragma unroll
            for (int np = 0; np < 2; np++) {
                int nrow = wn * 32 + np * 16 + (lane & 7) + ((lane >> 4) << 3);
                int c = ks * 2 + ((lane >> 3) & 1);
                ldmatrix_x4(bfr[np], Bb + nrow * 128 + ((c ^ (nrow & 7)) << 4));
            }
#pragma unroll
            for (int mt = 0; mt < 4; mt++)
#pragma unroll
                for (int nt = 0; nt < 4; nt++)
                    mma_bf16(acc[mt][nt], afr[mt],
                             bfr[nt >> 1][(nt & 1) * 2],
                             bfr[nt >> 1][(nt & 1) * 2 + 1]);
        }
    }

    __nv_bfloat16* stg = (__nv_bfloat16*)smem;     // [128][136]
    if (SYM) __syncthreads();

    const int tg = lane >> 2, tq = lane & 3;
#pragma unroll
    for (int mt = 0; mt < 4; mt++) {
#pragma unroll
        for (int nt = 0; nt < 4; nt++) {
            int r0 = wm * 64 + mt * 16 + tg;
            int cc = wn * 32 + nt * 8 + tq * 2;
            float b0 = 0.f, b1 = 0.f;
            if (bias) { b0 = bias[Ns + cc]; b1 = bias[Ns + cc + 1]; }
            float v00 = acc[mt][nt][0] * scale + b0;
            float v01 = acc[mt][nt][1] * scale + b1;
            float v10 = acc[mt][nt][2] * scale + b0;
            float v11 = acc[mt][nt][3] * scale + b1;
            if (OMODE == 0) {
                float* pC = (float*)C0p + (size_t)z * sC + Ms * ldc + Ns;
                float2 w0 = { v00, v01 }, w1 = { v10, v11 };
                *(float2*)(pC + (size_t)r0 * ldc + cc)       = w0;
                *(float2*)(pC + (size_t)(r0 + 8) * ldc + cc) = w1;
            } else if (OMODE == 1) {
                __nv_bfloat16* pC = (__nv_bfloat16*)C0p + (size_t)z * sC + Ms * ldc + Ns;
                __nv_bfloat16 h00 = __float2bfloat16(v00), h01 = __float2bfloat16(v01);
                __nv_bfloat16 h10 = __float2bfloat16(v10), h11 = __float2bfloat16(v11);
                *(__nv_bfloat162*)(pC + (size_t)r0 * ldc + cc) = __nv_bfloat162(h00, h01);
                *(__nv_bfloat162*)(pC + (size_t)(r0 + 8) * ldc + cc) = __nv_bfloat162(h10, h11);
                if (SYM) {
                    stg[r0 * 136 + cc]           = h00;
                    stg[r0 * 136 + cc + 1]       = h01;
                    stg[(r0 + 8) * 136 + cc]     = h10;
                    stg[(r0 + 8) * 136 + cc + 1] = h11;
                }
            } else {
                __nv_bfloat16* pH = (__nv_bfloat16*)C0p + (size_t)z * sC + Ms * ldc + Ns;
                __nv_bfloat16* pL = (__nv_bfloat16*)C1p + (size_t)z * sC + Ms * ldc + Ns;
                __nv_bfloat16 h00 = __float2bfloat16(v00), h01 = __float2bfloat16(v01);
                __nv_bfloat16 h10 = __float2bfloat16(v10), h11 = __float2bfloat16(v11);
                *(__nv_bfloat162*)(pH + (size_t)r0 * ldc + cc) = __nv_bfloat162(h00, h01);
                *(__nv_bfloat162*)(pH + (size_t)(r0 + 8) * ldc + cc) = __nv_bfloat162(h10, h11);
                *(__nv_bfloat162*)(pL + (size_t)r0 * ldc + cc) =
                    __nv_bfloat162(__float2bfloat16(v00 - __bfloat162float(h00)),
                                   __float2bfloat16(v01 - __bfloat162float(h01)));
                *(__nv_bfloat162*)(pL + (size_t)(r0 + 8) * ldc + cc) =
                    __nv_bfloat162(__float2bfloat16(v10 - __bfloat162float(h10)),
                                   __float2bfloat16(v11 - __bfloat162float(h11)));
            }
        }
    }

    if (SYM && ibl != jbl) {
        __syncthreads();
        __nv_bfloat16* pT = (__nv_bfloat16*)C0p + (size_t)z * sC + Ns * ldc + Ms;
        const int orow = tid >> 1;
        const int half = tid & 1;
#pragma unroll
        for (int q = 0; q < 8; q++) {
            int c0 = half * 64 + q * 8;
            __nv_bfloat16 tmp[8];
#pragma unroll
            for (int e = 0; e < 8; e++)
                tmp[e] = stg[(c0 + e) * 136 + orow];
            *(uint4*)(pT + (size_t)orow * ldc + c0) = *(uint4*)tmp;
        }
    }
}

// ---------------------------------------------------------------------------
// fp32 -> (bf16 hi, bf16 lo) split, 4 elements/thread
// ---------------------------------------------------------------------------
__global__ __launch_bounds__(256)
void conv_split(const float* __restrict__ in, __nv_bfloat16* __restrict__ hi,
                __nv_bfloat16* __restrict__ lo, int n)
{
    int i = (blockIdx.x * 256 + threadIdx.x) * 4;
    if (i >= n) return;
    float4 v = *(const float4*)(in + i);
    __nv_bfloat16 h0 = __float2bfloat16(v.x), h1 = __float2bfloat16(v.y);
    __nv_bfloat16 h2 = __float2bfloat16(v.z), h3 = __float2bfloat16(v.w);
    __nv_bfloat162 ph0(h0, h1), ph1(h2, h3);
    __nv_bfloat162 pl0(__float2bfloat16(v.x - __bfloat162float(h0)),
                       __float2bfloat16(v.y - __bfloat162float(h1)));
    __nv_bfloat162 pl1(__float2bfloat16(v.z - __bfloat162float(h2)),
                       __float2bfloat16(v.w - __bfloat162float(h3)));
    *(__nv_bfloat162*)(hi + i)     = ph0;
    *(__nv_bfloat162*)(hi + i + 2) = ph1;
    *(__nv_bfloat162*)(lo + i)     = pl0;
    *(__nv_bfloat162*)(lo + i + 2) = pl1;
}

// ---------------------------------------------------------------------------
// transpose + split (weights only): in [R][C] fp32 -> out [C][R] bf16 hi/lo
// ---------------------------------------------------------------------------
__global__ __launch_bounds__(256)
void transpose_split(const float* __restrict__ in, __nv_bfloat16* __restrict__ oh,
                     __nv_bfloat16* __restrict__ ol, int R, int C,
                     long long sIn, long long sOut)
{
    __shared__ float tile[32][33];
    const int c0 = blockIdx.x * 32, r0 = blockIdx.y * 32, z = blockIdx.z;
    in += (size_t)z * sIn; oh += (size_t)z * sOut; ol += (size_t)z * sOut;
    const int tx = threadIdx.x, ty = threadIdx.y;
#pragma unroll
    for (int j = 0; j < 4; j++)
        tile[ty + 8 * j][tx] = in[(size_t)(r0 + ty + 8 * j) * C + c0 + tx];
    __syncthreads();
#pragma unroll
    for (int j = 0; j < 4; j++) {
        float v = tile[tx][ty + 8 * j];
        __nv_bfloat16 h = __float2bfloat16(v);
        size_t o = (size_t)(c0 + ty + 8 * j) * R + r0 + tx;
        oh[o] = h;
        ol[o] = __float2bfloat16(v - __bfloat162float(h));
    }
}

// ---------------------------------------------------------------------------
// Row softmax on bf16 S -> bf16 hi/lo P. grid (4096, 1, B), 256 threads.
// ---------------------------------------------------------------------------
__global__ __launch_bounds__(256)
void softmax_split_b(const __nv_bfloat16* __restrict__ S,
                     __nv_bfloat16* __restrict__ Ph, __nv_bfloat16* __restrict__ Pl)
{
    const size_t row = (size_t)blockIdx.z * N_ + blockIdx.x;
    const uint4* r4 = (const uint4*)(S + row * N_);
    uint4* ph4 = (uint4*)(Ph + row * N_);
    uint4* pl4 = (uint4*)(Pl + row * N_);
    const int tid = threadIdx.x, lane = tid & 31, wid = tid >> 5;
    __shared__ float red[8];
    __shared__ float bval;

    uint4 u[2];
    u[0] = r4[tid];
    u[1] = r4[tid + 256];
    float v[16];
#pragma unroll
    for (int q = 0; q < 2; q++) {
        const uint32_t* w = (const uint32_t*)&u[q];
#pragma unroll
        for (int j = 0; j < 4; j++) {
            float2 f = __bfloat1622float2(*(const __nv_bfloat162*)&w[j]);
            v[q * 8 + j * 2]     = f.x;
            v[q * 8 + j * 2 + 1] = f.y;
        }
    }

    float mx = v[0];
#pragma unroll
    for (int j = 1; j < 16; j++) mx = fmaxf(mx, v[j]);
#pragma unroll
    for (int off = 16; off; off >>= 1)
        mx = fmaxf(mx, __shfl_xor_sync(0xffffffffu, mx, off));
    if (lane == 0) red[wid] = mx;
    __syncthreads();
    if (tid == 0) {
        float m = red[0];
#pragma unroll
        for (int i = 1; i < 8; i++) m = fmaxf(m, red[i]);
        bval = m;
    }
    __syncthreads();
    mx = bval;

    float s = 0.f;
#pragma unroll
    for (int j = 0; j < 16; j++) { v[j] = __expf(v[j] - mx); s += v[j]; }
#pragma unroll
    for (int off = 16; off; off >>= 1)
        s += __shfl_xor_sync(0xffffffffu, s, off);
    if (lane == 0) red[wid] = s;
    __syncthreads();
    if (tid == 0) {
        float t = 0.f;
#pragma unroll
        for (int i = 0; i < 8; i++) t += red[i];
        bval = 1.f / t;
    }
    __syncthreads();
    const float inv = bval;

    uint4 oh[2], ol[2];
#pragma unroll
    for (int q = 0; q < 2; q++) {
        uint32_t* wh = (uint32_t*)&oh[q];
        uint32_t* wl = (uint32_t*)&ol[q];
#pragma unroll
        for (int j = 0; j < 4; j++) {
            float a = v[q * 8 + j * 2] * inv;
            float b = v[q * 8 + j * 2 + 1] * inv;
            __nv_bfloat16 ha = __float2bfloat16(a), hb = __float2bfloat16(b);
            __nv_bfloat162 hp(ha, hb);
            __nv_bfloat162 lp(__float2bfloat16(a - __bfloat162float(ha)),
                              __float2bfloat16(b - __bfloat162float(hb)));
            wh[j] = *(uint32_t*)&hp;
            wl[j] = *(uint32_t*)&lp;
        }
    }
    ph4[tid]       = oh[0];
    ph4[tid + 256] = oh[1];
    pl4[tid]       = ol[0];
    pl4[tid + 256] = ol[1];
}

// ---------------------------------------------------------------------------
// Hyperedge branch
// ---------------------------------------------------------------------------
__global__ __launch_bounds__(256)
void edge_mean_kernel(const float* __restrict__ x, const int* __restrict__ Hm)
{
    const int e = blockIdx.x, b = blockIdx.y, f = threadIdx.x;
    const float* xb = x + (size_t)b * N_ * F_;
    float sum = 0.f;
    int cnt = 0;
    for (int n = 0; n < N_; n++) {
        if (Hm[(size_t)n * E_ + e]) {
            sum += xb[(size_t)n * F_ + f];
            cnt++;
        }
    }
    const float deg = (float)cnt;
    g_mean[((size_t)b * MAXE + e) * F_ + f] = sum / fmaxf(deg, 1.0f);
    if (f == 0 && b == 0) g_deg[e] = deg;
}

__global__ __launch_bounds__(128)
void ctx_kernel(const float* __restrict__ m1w, const float* __restrict__ m1b,
                const float* __restrict__ m2w, const float* __restrict__ m2b,
                const float* __restrict__ m3w, const float* __restrict__ m3b)
{
    const int e = blockIdx.x, b = blockIdx.y, t = threadIdx.x;
    __shared__ float ms[F_];
    __shared__ float h1[H1_];
    __shared__ float h2[H2_];
    __shared__ float red[4];

    const float* mp = g_mean + ((size_t)b * MAXE + e) * F_;
    ms[t]       = mp[t];
    ms[t + 128] = mp[t + 128];
    __syncthreads();

    float s = m1b[t];
    for (int k = 0; k < F_; k++) s += ms[k] * m1w[k * H1_ + t];
    h1[t] = fmaxf(s, 0.f);
    __syncthreads();

    if (t < H2_) {
        float s2 = m2b[t];
        for (int k = 0; k < H1_; k++) s2 += h1[k] * m2w[k * H2_ + t];
        h2[t] = fmaxf(s2, 0.f);
    }
    __syncthreads();

    float p = (t < H2_) ? h2[t] * m3w[t] : 0.f;
#pragma unroll
    for (int off = 16; off; off >>= 1)
        p += __shfl_xor_sync(0xffffffffu, p, off);
    if ((t & 31) == 0) red[t >> 5] = p;
    __syncthreads();
    if (t == 0)
        g_ctx[b * MAXE + e] = red[0] + red[1] + red[2] + red[3] + m3b[0];
}

__global__ __launch_bounds__(256)
void aw_kernel(const float* __restrict__ x, const int* __restrict__ Hm,
               const float* __restrict__ cw, const float* __restrict__ cb,
               const float* __restrict__ hb, const float* __restrict__ alpha,
               float* __restrict__ out)
{
    const int n = blockIdx.x, b = blockIdx.y, t = threadIdx.x;
    __shared__ float red[8];
    __shared__ float compat_s;

    float p = x[((size_t)b * N_ + n) * F_ + t] * cw[t];
#pragma unroll
    for (int off = 16; off; off >>= 1)
        p += __shfl_xor_sync(0xffffffffu, p, off);
    if ((t & 31) == 0) red[t >> 5] = p;
    __syncthreads();
    if (t == 0) {
        float s = 0.f;
#pragma unroll
        for (int i = 0; i < 8; i++) s += red[i];
        compat_s = s + cb[0] + hb[0];
    }
    __syncthreads();

    float val = 0.f;
    if (t < MAXE) {
        if (Hm[(size_t)n * E_ + t] && g_deg[t] > 1.0f) {
            float z = compat_s + alpha[0] * g_ctx[b * MAXE + t];
            val = 1.f / (1.f + __expf(-z));
        }
    }
    out[((size_t)b * N_ + n) * OUTC + t] = val;
}

// ---------------------------------------------------------------------------
// Launch
// ---------------------------------------------------------------------------
extern "C" void kernel_launch(void* const* d_in, const int* in_sizes, int n_in,
                              void* d_out, int out_size)
{
    const float* x      = (const float*)d_in[0];
    const int*   Hm     = (const int*)  d_in[1];
    const float* weight = (const float*)d_in[2];
    const float* bias   = (const float*)d_in[3];
    const float* Wn_w   = (const float*)d_in[4];
    const float* Wn_b   = (const float*)d_in[5];
    const float* m1_w   = (const float*)d_in[6];
    const float* m1_b   = (const float*)d_in[7];
    const float* m2_w   = (const float*)d_in[8];
    const float* m2_b   = (const float*)d_in[9];
    const float* m3_w   = (const float*)d_in[10];
    const float* m3_b   = (const float*)d_in[11];
    const float* c_w    = (const float*)d_in[12];
    const float* c_b    = (const float*)d_in[13];
    const float* hedgeb = (const float*)d_in[14];
    const float* alpha  = (const float*)d_in[15];
    float* out = (float*)d_out;

    __nv_bfloat16 *Sb, *xh, *xl, *xph, *xpl, *vth, *Ph, *Pl;
    __nv_bfloat16 *wth, *wtl, *wnth, *wntl;
    cudaGetSymbolAddress((void**)&Sb,  g_Sb);
    cudaGetSymbolAddress((void**)&xh,  g_xh);
    cudaGetSymbolAddress((void**)&xl,  g_xl);
    cudaGetSymbolAddress((void**)&xph, g_xph);
    cudaGetSymbolAddress((void**)&xpl, g_xpl);
    cudaGetSymbolAddress((void**)&vth, g_vth);
    cudaGetSymbolAddress((void**)&Ph,  g_Ph);
    cudaGetSymbolAddress((void**)&Pl,  g_Pl);
    cudaGetSymbolAddress((void**)&wth, g_wth);
    cudaGetSymbolAddress((void**)&wtl, g_wtl);
    cudaGetSymbolAddress((void**)&wnth, g_wnth);
    cudaGetSymbolAddress((void**)&wntl, g_wntl);

    cudaFuncSetAttribute(gemm_bf16s<2, 0, 0>,
                         cudaFuncAttributeMaxDynamicSharedMemorySize, GEMM_SMEM);
    cudaFuncSetAttribute(gemm_bf16s<2, 2, 0>,
                         cudaFuncAttributeMaxDynamicSharedMemorySize, GEMM_SMEM);
    cudaFuncSetAttribute(gemm_bf16s<2, 1, 0>,
                         cudaFuncAttributeMaxDynamicSharedMemorySize, GEMM_SMEM);
    cudaFuncSetAttribute(gemm_bf16s<2, 1, 1>,
                         cudaFuncAttributeMaxDynamicSharedMemorySize, GEMM_SMEM);

    const int nx = B_ * N_ * F_;   // 4M elements

    // hyperedge branch (independent)
    edge_mean_kernel<<<dim3(MAXE, B_), 256>>>(x, Hm);
    ctx_kernel<<<dim3(MAXE, B_), 128>>>(m1_w, m1_b, m2_w, m2_b, m3_w, m3_b);
    aw_kernel<<<dim3(N_, B_), 256>>>(x, Hm, c_w, c_b, hedgeb, alpha, out);

    // input conversions
    conv_split<<<nx / 4 / 256, 256>>>(x, xh, xl, nx);
    transpose_split<<<dim3(8, 8, 1), dim3(32, 8)>>>(weight, wth, wtl, F_, F_, 0, 0);
    transpose_split<<<dim3(8, 8, 1), dim3(32, 8)>>>(Wn_w, wnth, wntl, F_, F_, 0, 0);

    // xp = x@Wn_w + Wn_b (2-pass: xh*Wh + xl*Wh; bf16 hi/lo emitted)
    gemm_bf16s<2, 2, 0><<<dim3(F_ / 128, (B_ * N_) / 128, 1), 256, GEMM_SMEM>>>(
        xh, xl, wnth, wntl, xph, xpl, Wn_b, F_, F_, 0, 0, 0, 1.0f);

    // v^T[f][n] = sum_k weight^T[f][k]*x[n][k] (2-pass; bf16 hi only)
    gemm_bf16s<2, 1, 0><<<dim3(N_ / 128, F_ / 128, B_), 256, GEMM_SMEM>>>(
        wth, wtl, xh, xl, vth, nullptr, nullptr, F_, N_,
        0, (long long)N_ * F_, (long long)F_ * N_, 1.0f);

    // S = xp @ xp^T / 16 -> bf16, symmetric: 528 upper-triangle tiles + mirror
    // (A and B are BOTH xph/xpl — B args must mirror A args)
    gemm_bf16s<2, 1, 1><<<dim3(528, 1, B_), 256, GEMM_SMEM>>>(
        xph, xpl, xph, xpl, Sb, nullptr, nullptr, F_, N_,
        (long long)N_ * F_, (long long)N_ * F_, (long long)N_ * N_, 0.0625f);

    // P = softmax(S) -> bf16 hi/lo
    softmax_split_b<<<dim3(N_, 1, B_), 256>>>(Sb, Ph, Pl);

    // y = P @ V + bias -> out[..., E:E+F]  (2-pass: Ph*Vh + Pl*Vh)
    gemm_bf16s<2, 0, 0><<<dim3(F_ / 128, N_ / 128, B_), 256, GEMM_SMEM>>>(
        Ph, Pl, vth, nullptr, out + E_, nullptr, bias, N_, OUTC,
        (long long)N_ * N_, (long long)F_ * N_, (long long)N_ * OUTC, 1.0f);
}

// round 17
// speedup vs baseline: 1.5563x; 1.3106x over previous
#include <cuda_runtime.h>
#include <cuda_fp16.h>
#include <cstdint>
#include <cstddef>

// Problem constants
#define B_   4
#define N_   4096
#define E_   256
#define F_   256
#define MAXE 50
#define H1_  128
#define H2_  64
#define OUTC 512

// ---------------------------------------------------------------------------
// Static device scratch (all fp16 single precision-path)
// ---------------------------------------------------------------------------
__device__ __half g_S16[67108864];            // scores fp16 (128 MB)
__device__ __half g_P16[67108864];            // softmax(S) fp16 (128 MB)
__device__ __half g_x16 [B_ * N_ * F_];       // x fp16
__device__ __half g_xp16[B_ * N_ * F_];       // xp fp16
__device__ __half g_vt16[B_ * F_ * N_];       // v^T fp16 [b][256][4096]
__device__ __half g_wt16 [F_ * F_];           // weight^T fp16
__device__ __half g_wnt16[F_ * F_];           // Wn_w^T fp16
__device__ float g_mean[B_ * MAXE * F_];
__device__ float g_ctx [B_ * MAXE];
__device__ float g_deg [MAXE];

// ---------------------------------------------------------------------------
// PTX helpers (base sm_100-safe: mma.sync / ldmatrix / cp.async)
// ---------------------------------------------------------------------------
__device__ __forceinline__ uint32_t smem_u32(const void* p) {
    uint32_t a;
    asm("{ .reg .u64 t; cvta.to.shared.u64 t, %1; cvt.u32.u64 %0, t; }"
        : "=r"(a) : "l"(p));
    return a;
}
__device__ __forceinline__ void cp_async16(uint32_t s, const void* g) {
    asm volatile("cp.async.cg.shared.global [%0], [%1], 16;\n"
        :: "r"(s), "l"((unsigned long long)__cvta_generic_to_global(g)) : "memory");
}
__device__ __forceinline__ void cp_commit() {
    asm volatile("cp.async.commit_group;\n" ::: "memory");
}
__device__ __forceinline__ void cp_wait0() {
    asm volatile("cp.async.wait_group 0;\n" ::: "memory");
}
__device__ __forceinline__ void cp_wait1() {
    asm volatile("cp.async.wait_group 1;\n" ::: "memory");
}
__device__ __forceinline__ void ldmatrix_x4(uint32_t* r, uint32_t addr) {
    asm volatile("ldmatrix.sync.aligned.m8n8.x4.shared.b16 {%0,%1,%2,%3}, [%4];\n"
        : "=r"(r[0]), "=r"(r[1]), "=r"(r[2]), "=r"(r[3]) : "r"(addr));
}
__device__ __forceinline__ void mma_f16(float* d, const uint32_t* a,
                                        uint32_t b0, uint32_t b1) {
    asm volatile(
        "mma.sync.aligned.m16n8k16.row.col.f32.f16.f16.f32 "
        "{%0,%1,%2,%3}, {%4,%5,%6,%7}, {%8,%9}, {%0,%1,%2,%3};\n"
        : "+f"(d[0]), "+f"(d[1]), "+f"(d[2]), "+f"(d[3])
        : "r"(a[0]), "r"(a[1]), "r"(a[2]), "r"(a[3]), "r"(b0), "r"(b1));
}

// ---------------------------------------------------------------------------
// fp16 GEMM via mma.sync (proven 128x128 config, single pass):
// D[m][n] = scale*sum_k A[m,k]*B[n,k] (+bias[n])
// OMODE=0: fp32 out. OMODE=1: fp16 out.
// SYM=1: A==B; grid.x enumerates 528 upper-triangle 128x128 tile pairs;
//        each CTA also writes the transposed mirror (requires OMODE==1).
// CTA tile 128x128, K-chunk 64, 256 threads (8 warps 2m x 4n, warp 64x32).
// Smem: 3 stages x 32KB = 96KB. Depth-2 cp.async prefetch.
// ---------------------------------------------------------------------------
#define GEMM_SMEM (3 * 32768)

template <int OMODE, int SYM>
__global__ __launch_bounds__(256)
void gemm_f16k(const __half* __restrict__ A, const __half* __restrict__ B,
               void* __restrict__ C0p, const float* __restrict__ bias,
               int K, int ldc, long long sA, long long sB, long long sC,
               float scale)
{
    extern __shared__ __align__(16) char smem[];
    const uint32_t sbase = smem_u32(smem);
    const int tid = threadIdx.x;
    const int lane = tid & 31;
    const int wid = tid >> 5;
    const int wm = wid & 1;
    const int wn = wid >> 1;

    size_t Ms, Ns;
    int ibl = 0, jbl = 0;
    if (SYM) {
        const int NT = 32;
        int t = blockIdx.x;
        int i = (int)((2.f * NT + 1.f -
                       sqrtf((2.f * NT + 1.f) * (2.f * NT + 1.f) - 8.f * t)) * 0.5f);
        while ((i + 1) * NT - ((i + 1) * i) / 2 <= t) i++;
        while (i * NT - (i * (i - 1)) / 2 > t) i--;
        int j = i + (t - (i * NT - (i * (i - 1)) / 2));
        ibl = i; jbl = j;
        Ms = (size_t)i * 128;
        Ns = (size_t)j * 128;
    } else {
        Ms = (size_t)blockIdx.y * 128;
        Ns = (size_t)blockIdx.x * 128;
    }
    const int z = blockIdx.z;
    const __half* pA = A + (size_t)z * sA + Ms * K;
    const __half* pB = B + (size_t)z * sB + Ns * K;

    const int T = K >> 6;

    float acc[4][4][4];
#pragma unroll
    for (int i = 0; i < 4; i++)
#pragma unroll
        for (int j = 0; j < 4; j++)
#pragma unroll
            for (int k = 0; k < 4; k++) acc[i][j][k] = 0.f;

    auto load_chunk = [&](int t) {
        const int kk = t << 6;
        const uint32_t st = sbase + (t % 3) * 32768;
#pragma unroll
        for (int i = 0; i < 4; i++) {
            int idx = i * 256 + tid;
            int row = idx >> 3, c = idx & 7;
            uint32_t sa = st + row * 128 + ((c ^ (row & 7)) << 4);
            cp_async16(sa, pA + (size_t)row * K + kk + c * 8);
        }
#pragma unroll
        for (int i = 0; i < 4; i++) {
            int idx = i * 256 + tid;
            int row = idx >> 3, c = idx & 7;
            uint32_t sa = st + 16384 + row * 128 + ((c ^ (row & 7)) << 4);
            cp_async16(sa, pB + (size_t)row * K + kk + c * 8);
        }
        cp_commit();
    };

    load_chunk(0);
    load_chunk(1);

#pragma unroll 1
    for (int t = 0; t < T; t++) {
        if (t + 1 < T) cp_wait1(); else cp_wait0();
        __syncthreads();
        if (t + 2 < T) load_chunk(t + 2);

        const uint32_t Ab = sbase + (t % 3) * 32768;
        const uint32_t Bb = Ab + 16384;
#pragma unroll
        for (int ks = 0; ks < 4; ks++) {
            uint32_t afr[4][4];
#pragma unroll
            for (int mt = 0; mt < 4; mt++) {
                int arow = wm * 64 + mt * 16 + (lane & 15);
                int c = ks * 2 + (lane >> 4);
                ldmatrix_x4(afr[mt], Ab + arow * 128 + ((c ^ (arow & 7)) << 4));
            }
            uint32_t bfr[2][4];
#pragma unroll
            for (int np = 0; np < 2; np++) {
                int nrow = wn * 32 + np * 16 + (lane & 7) + ((lane >> 4) << 3);
                int c = ks * 2 + ((lane >> 3) & 1);
                ldmatrix_x4(bfr[np], Bb + nrow * 128 + ((c ^ (nrow & 7)) << 4));
            }
#pragma unroll
            for (int mt = 0; mt < 4; mt++)
#pragma unroll
                for (int nt = 0; nt < 4; nt++)
                    mma_f16(acc[mt][nt], afr[mt],
                            bfr[nt >> 1][(nt & 1) * 2],
                            bfr[nt >> 1][(nt & 1) * 2 + 1]);
        }
    }

    __half* stg = (__half*)smem;     // [128][136]
    if (SYM) __syncthreads();

    const int tg = lane >> 2, tq = lane & 3;
#pragma unroll
    for (int mt = 0; mt < 4; mt++) {
#pragma unroll
        for (int nt = 0; nt < 4; nt++) {
            int r0 = wm * 64 + mt * 16 + tg;
            int cc = wn * 32 + nt * 8 + tq * 2;
            float b0 = 0.f, b1 = 0.f;
            if (bias) { b0 = bias[Ns + cc]; b1 = bias[Ns + cc + 1]; }
            float v00 = acc[mt][nt][0] * scale + b0;
            float v01 = acc[mt][nt][1] * scale + b1;
            float v10 = acc[mt][nt][2] * scale + b0;
            float v11 = acc[mt][nt][3] * scale + b1;
            if (OMODE == 0) {
                float* pC = (float*)C0p + (size_t)z * sC + Ms * ldc + Ns;
                float2 w0 = { v00, v01 }, w1 = { v10, v11 };
                *(float2*)(pC + (size_t)r0 * ldc + cc)       = w0;
                *(float2*)(pC + (size_t)(r0 + 8) * ldc + cc) = w1;
            } else {
                __half* pC = (__half*)C0p + (size_t)z * sC + Ms * ldc + Ns;
                __half h00 = __float2half(v00), h01 = __float2half(v01);
                __half h10 = __float2half(v10), h11 = __float2half(v11);
                *(__half2*)(pC + (size_t)r0 * ldc + cc) = __half2(h00, h01);
                *(__half2*)(pC + (size_t)(r0 + 8) * ldc + cc) = __half2(h10, h11);
                if (SYM) {
                    stg[r0 * 136 + cc]           = h00;
                    stg[r0 * 136 + cc + 1]       = h01;
                    stg[(r0 + 8) * 136 + cc]     = h10;
                    stg[(r0 + 8) * 136 + cc + 1] = h11;
                }
            }
        }
    }

    if (SYM && ibl != jbl) {
        __syncthreads();
        __half* pT = (__half*)C0p + (size_t)z * sC + Ns * ldc + Ms;
        const int orow = tid >> 1;
        const int half_ = tid & 1;
#pragma unroll
        for (int q = 0; q < 8; q++) {
            int c0 = half_ * 64 + q * 8;
            __half tmp[8];
#pragma unroll
            for (int e = 0; e < 8; e++)
                tmp[e] = stg[(c0 + e) * 136 + orow];
            *(uint4*)(pT + (size_t)orow * ldc + c0) = *(uint4*)tmp;
        }
    }
}

// ---------------------------------------------------------------------------
// fp32 -> fp16 convert, 8 elements/thread (16B store)
// ---------------------------------------------------------------------------
__global__ __launch_bounds__(256)
void conv_half(const float* __restrict__ in, __half* __restrict__ out, int n)
{
    int i = (blockIdx.x * 256 + threadIdx.x) * 8;
    if (i >= n) return;
    float4 a = *(const float4*)(in + i);
    float4 b = *(const float4*)(in + i + 4);
    __half h[8];
    h[0] = __float2half(a.x); h[1] = __float2half(a.y);
    h[2] = __float2half(a.z); h[3] = __float2half(a.w);
    h[4] = __float2half(b.x); h[5] = __float2half(b.y);
    h[6] = __float2half(b.z); h[7] = __float2half(b.w);
    *(uint4*)(out + i) = *(uint4*)h;
}

// ---------------------------------------------------------------------------
// transpose fp32 [R][C] -> fp16 [C][R]. block (32,8)
// ---------------------------------------------------------------------------
__global__ __launch_bounds__(256)
void transpose_half(const float* __restrict__ in, __half* __restrict__ out,
                    int R, int C)
{
    __shared__ float tile[32][33];
    const int c0 = blockIdx.x * 32, r0 = blockIdx.y * 32;
    const int tx = threadIdx.x, ty = threadIdx.y;
#pragma unroll
    for (int j = 0; j < 4; j++)
        tile[ty + 8 * j][tx] = in[(size_t)(r0 + ty + 8 * j) * C + c0 + tx];
    __syncthreads();
#pragma unroll
    for (int j = 0; j < 4; j++)
        out[(size_t)(c0 + ty + 8 * j) * R + r0 + tx] =
            __float2half(tile[tx][ty + 8 * j]);
}

// ---------------------------------------------------------------------------
// Row softmax fp16 S -> fp16 P. grid (4096, 1, B), 256 threads, 16 elem/thr.
// ---------------------------------------------------------------------------
__global__ __launch_bounds__(256)
void softmax_h(const __half* __restrict__ S, __half* __restrict__ P)
{
    const size_t row = (size_t)blockIdx.z * N_ + blockIdx.x;
    const uint4* r4 = (const uint4*)(S + row * N_);
    uint4* p4 = (uint4*)(P + row * N_);
    const int tid = threadIdx.x, lane = tid & 31, wid = tid >> 5;
    __shared__ float red[8];
    __shared__ float bval;

    uint4 u[2];
    u[0] = r4[tid];
    u[1] = r4[tid + 256];
    float v[16];
#pragma unroll
    for (int q = 0; q < 2; q++) {
        const uint32_t* w = (const uint32_t*)&u[q];
#pragma unroll
        for (int j = 0; j < 4; j++) {
            float2 f = __half22float2(*(const __half2*)&w[j]);
            v[q * 8 + j * 2]     = f.x;
            v[q * 8 + j * 2 + 1] = f.y;
        }
    }

    float mx = v[0];
#pragma unroll
    for (int j = 1; j < 16; j++) mx = fmaxf(mx, v[j]);
#pragma unroll
    for (int off = 16; off; off >>= 1)
        mx = fmaxf(mx, __shfl_xor_sync(0xffffffffu, mx, off));
    if (lane == 0) red[wid] = mx;
    __syncthreads();
    if (tid == 0) {
        float m = red[0];
#pragma unroll
        for (int i = 1; i < 8; i++) m = fmaxf(m, red[i]);
        bval = m;
    }
    __syncthreads();
    mx = bval;

    float s = 0.f;
#pragma unroll
    for (int j = 0; j < 16; j++) { v[j] = __expf(v[j] - mx); s += v[j]; }
#pragma unroll
    for (int off = 16; off; off >>= 1)
        s += __shfl_xor_sync(0xffffffffu, s, off);
    if (lane == 0) red[wid] = s;
    __syncthreads();
    if (tid == 0) {
        float t = 0.f;
#pragma unroll
        for (int i = 0; i < 8; i++) t += red[i];
        bval = 1.f / t;
    }
    __syncthreads();
    const float inv = bval;

    uint4 o[2];
#pragma unroll
    for (int q = 0; q < 2; q++) {
        uint32_t* w = (uint32_t*)&o[q];
#pragma unroll
        for (int j = 0; j < 4; j++) {
            __half2 hp(__float2half(v[q * 8 + j * 2] * inv),
                       __float2half(v[q * 8 + j * 2 + 1] * inv));
            w[j] = *(uint32_t*)&hp;
        }
    }
    p4[tid]       = o[0];
    p4[tid + 256] = o[1];
}

// ---------------------------------------------------------------------------
// Hyperedge branch (exact fp32, unchanged)
// ---------------------------------------------------------------------------
__global__ __launch_bounds__(256)
void edge_mean_kernel(const float* __restrict__ x, const int* __restrict__ Hm)
{
    const int e = blockIdx.x, b = blockIdx.y, f = threadIdx.x;
    const float* xb = x + (size_t)b * N_ * F_;
    float sum = 0.f;
    int cnt = 0;
    for (int n = 0; n < N_; n++) {
        if (Hm[(size_t)n * E_ + e]) {
            sum += xb[(size_t)n * F_ + f];
            cnt++;
        }
    }
    const float deg = (float)cnt;
    g_mean[((size_t)b * MAXE + e) * F_ + f] = sum / fmaxf(deg, 1.0f);
    if (f == 0 && b == 0) g_deg[e] = deg;
}

__global__ __launch_bounds__(128)
void ctx_kernel(const float* __restrict__ m1w, const float* __restrict__ m1b,
                const float* __restrict__ m2w, const float* __restrict__ m2b,
                const float* __restrict__ m3w, const float* __restrict__ m3b)
{
    const int e = blockIdx.x, b = blockIdx.y, t = threadIdx.x;
    __shared__ float ms[F_];
    __shared__ float h1[H1_];
    __shared__ float h2[H2_];
    __shared__ float red[4];

    const float* mp = g_mean + ((size_t)b * MAXE + e) * F_;
    ms[t]       = mp[t];
    ms[t + 128] = mp[t + 128];
    __syncthreads();

    float s = m1b[t];
    for (int k = 0; k < F_; k++) s += ms[k] * m1w[k * H1_ + t];
    h1[t] = fmaxf(s, 0.f);
    __syncthreads();

    if (t < H2_) {
        float s2 = m2b[t];
        for (int k = 0; k < H1_; k++) s2 += h1[k] * m2w[k * H2_ + t];
        h2[t] = fmaxf(s2, 0.f);
    }
    __syncthreads();

    float p = (t < H2_) ? h2[t] * m3w[t] : 0.f;
#pragma unroll
    for (int off = 16; off; off >>= 1)
        p += __shfl_xor_sync(0xffffffffu, p, off);
    if ((t & 31) == 0) red[t >> 5] = p;
    __syncthreads();
    if (t == 0)
        g_ctx[b * MAXE + e] = red[0] + red[1] + red[2] + red[3] + m3b[0];
}

__global__ __launch_bounds__(256)
void aw_kernel(const float* __restrict__ x, const int* __restrict__ Hm,
               const float* __restrict__ cw, const float* __restrict__ cb,
               const float* __restrict__ hb, const float* __restrict__ alpha,
               float* __restrict__ out)
{
    const int n = blockIdx.x, b = blockIdx.y, t = threadIdx.x;
    __shared__ float red[8];
    __shared__ float compat_s;

    float p = x[((size_t)b * N_ + n) * F_ + t] * cw[t];
#pragma unroll
    for (int off = 16; off; off >>= 1)
        p += __shfl_xor_sync(0xffffffffu, p, off);
    if ((t & 31) == 0) red[t >> 5] = p;
    __syncthreads();
    if (t == 0) {
        float s = 0.f;
#pragma unroll
        for (int i = 0; i < 8; i++) s += red[i];
        compat_s = s + cb[0] + hb[0];
    }
    __syncthreads();

    float val = 0.f;
    if (t < MAXE) {
        if (Hm[(size_t)n * E_ + t] && g_deg[t] > 1.0f) {
            float z = compat_s + alpha[0] * g_ctx[b * MAXE + t];
            val = 1.f / (1.f + __expf(-z));
        }
    }
    out[((size_t)b * N_ + n) * OUTC + t] = val;
}

// ---------------------------------------------------------------------------
// Launch
// ---------------------------------------------------------------------------
extern "C" void kernel_launch(void* const* d_in, const int* in_sizes, int n_in,
                              void* d_out, int out_size)
{
    const float* x      = (const float*)d_in[0];
    const int*   Hm     = (const int*)  d_in[1];
    const float* weight = (const float*)d_in[2];
    const float* bias   = (const float*)d_in[3];
    const float* Wn_w   = (const float*)d_in[4];
    const float* Wn_b   = (const float*)d_in[5];
    const float* m1_w   = (const float*)d_in[6];
    const float* m1_b   = (const float*)d_in[7];
    const float* m2_w   = (const float*)d_in[8];
    const float* m2_b   = (const float*)d_in[9];
    const float* m3_w   = (const float*)d_in[10];
    const float* m3_b   = (const float*)d_in[11];
    const float* c_w    = (const float*)d_in[12];
    const float* c_b    = (const float*)d_in[13];
    const float* hedgeb = (const float*)d_in[14];
    const float* alpha  = (const float*)d_in[15];
    float* out = (float*)d_out;

    __half *S16, *P16, *x16, *xp16, *vt16, *wt16, *wnt16;
    cudaGetSymbolAddress((void**)&S16,  g_S16);
    cudaGetSymbolAddress((void**)&P16,  g_P16);
    cudaGetSymbolAddress((void**)&x16,  g_x16);
    cudaGetSymbolAddress((void**)&xp16, g_xp16);
    cudaGetSymbolAddress((void**)&vt16, g_vt16);
    cudaGetSymbolAddress((void**)&wt16, g_wt16);
    cudaGetSymbolAddress((void**)&wnt16, g_wnt16);

    cudaFuncSetAttribute(gemm_f16k<0, 0>,
                         cudaFuncAttributeMaxDynamicSharedMemorySize, GEMM_SMEM);
    cudaFuncSetAttribute(gemm_f16k<1, 0>,
                         cudaFuncAttributeMaxDynamicSharedMemorySize, GEMM_SMEM);
    cudaFuncSetAttribute(gemm_f16k<1, 1>,
                         cudaFuncAttributeMaxDynamicSharedMemorySize, GEMM_SMEM);

    const int nx = B_ * N_ * F_;   // 4M elements

    // hyperedge branch (independent, exact fp32)
    edge_mean_kernel<<<dim3(MAXE, B_), 256>>>(x, Hm);
    ctx_kernel<<<dim3(MAXE, B_), 128>>>(m1_w, m1_b, m2_w, m2_b, m3_w, m3_b);
    aw_kernel<<<dim3(N_, B_), 256>>>(x, Hm, c_w, c_b, hedgeb, alpha, out);

    // input conversions
    conv_half<<<nx / 8 / 256, 256>>>(x, x16, nx);
    transpose_half<<<dim3(8, 8), dim3(32, 8)>>>(weight, wt16, F_, F_);
    transpose_half<<<dim3(8, 8), dim3(32, 8)>>>(Wn_w, wnt16, F_, F_);

    // xp = x@Wn_w + Wn_b -> fp16
    gemm_f16k<1, 0><<<dim3(F_ / 128, (B_ * N_) / 128, 1), 256, GEMM_SMEM>>>(
        x16, wnt16, xp16, Wn_b, F_, F_, 0, 0, 0, 1.0f);

    // v^T[f][n] = sum_k weight^T[f][k]*x[n][k] -> fp16 [F][N]
    gemm_f16k<1, 0><<<dim3(N_ / 128, F_ / 128, B_), 256, GEMM_SMEM>>>(
        wt16, x16, vt16, nullptr, F_, N_,
        0, (long long)N_ * F_, (long long)F_ * N_, 1.0f);

    // S = xp @ xp^T / 16 -> fp16, symmetric: 528 tiles + mirror
    gemm_f16k<1, 1><<<dim3(528, 1, B_), 256, GEMM_SMEM>>>(
        xp16, xp16, S16, nullptr, F_, N_,
        (long long)N_ * F_, (long long)N_ * F_, (long long)N_ * N_, 0.0625f);

    // P = softmax(S) -> fp16
    softmax_h<<<dim3(N_, 1, B_), 256>>>(S16, P16);

    // y = P @ V + bias -> out[..., E:E+F] (fp32)
    gemm_f16k<0, 0><<<dim3(F_ / 128, N_ / 128, B_), 256, GEMM_SMEM>>>(
        P16, vt16, out + E_, bias, N_, OUTC,
        (long long)N_ * N_, (long long)F_ * N_, (long long)N_ * OUTC, 1.0f);
}